// round 13
// baseline (speedup 1.0000x reference)
#include <cuda_runtime.h>
#include <cuda_fp16.h>
#include <math.h>
#include <stdint.h>

// ---------------------------------------------------------------------------
// Problem constants
// ---------------------------------------------------------------------------
#define Bz   4
#define Sz   1024
#define Dz   1024
#define Hh   16
#define Gg   8
#define HDz  64
#define Ez   8
#define EDz  2048
#define GHz  512
#define Tz   (Bz*Sz)          // 4096 tokens
#define QKVN 2560             // packed q(512) | k(1024) | v(1024)

// ---------------------------------------------------------------------------
// Scratch (static device memory)
// ---------------------------------------------------------------------------
__device__ __half g_h1h [Tz*Dz];
__device__ __half g_qkvh[(size_t)Tz*QKVN];
__device__ __half g_aoh [Tz*Dz];
__device__ float  g_x1  [Tz*Dz];
__device__ __half g_h2h [Tz*Dz];       // LN2 out, fp16 hi
__device__ __half g_h2l [Tz*Dz];       // LN2 out, fp16 lo (residual)
__device__ float  g_gh  [Tz*GHz];
__device__ float  g_w   [Tz*2];
__device__ int    g_cnt [Ez];
__device__ int    g_elist[Ez*Tz];
__device__ __half g_hidh[(size_t)Ez*Tz*EDz];   // per-expert dense rows (e*Tz + m)
__device__ __half g_eo  [(size_t)Tz*2*Dz];
// fp16 weights ([K][N] row-major; qkv packed) + packed qkv bias
__device__ __half g_wqkvh[(size_t)Dz*QKVN];
__device__ __half g_woh  [(size_t)Dz*Dz];
__device__ __half g_ew1h [(size_t)Ez*Dz*EDz];
__device__ __half g_ew2h [(size_t)Ez*EDz*Dz];
__device__ __half g_gw1h [(size_t)Dz*GHz];   // gate w1 hi
__device__ __half g_gw1l [(size_t)Dz*GHz];   // gate w1 lo
__device__ float  g_qkvb [QKVN];

// ---------------------------------------------------------------------------
// Helpers
// ---------------------------------------------------------------------------
__device__ __forceinline__ uint32_t s2u(const void* p){
    return (uint32_t)__cvta_generic_to_shared(p);
}
__device__ __forceinline__ void cpa16(uint32_t d, const void* s, bool v){
    asm volatile("cp.async.cg.shared.global [%0], [%1], 16, %2;\n"
                 :: "r"(d), "l"(s), "r"(v ? 16 : 0));
}
__device__ __forceinline__ void cp_commit(){ asm volatile("cp.async.commit_group;\n"); }
__device__ __forceinline__ void cp_wait0(){ asm volatile("cp.async.wait_group 0;\n"); }
__device__ __forceinline__ void cp_wait1(){ asm volatile("cp.async.wait_group 1;\n"); }
__device__ __forceinline__ void mma16(float* c, const uint32_t* a, uint32_t b0, uint32_t b1){
    asm volatile("mma.sync.aligned.m16n8k16.row.col.f32.f16.f16.f32 "
        "{%0,%1,%2,%3},{%4,%5,%6,%7},{%8,%9},{%0,%1,%2,%3};\n"
        : "+f"(c[0]),"+f"(c[1]),"+f"(c[2]),"+f"(c[3])
        : "r"(a[0]),"r"(a[1]),"r"(a[2]),"r"(a[3]),"r"(b0),"r"(b1));
}
__device__ __forceinline__ void ldm4(uint32_t* r, uint32_t addr){
    asm volatile("ldmatrix.sync.aligned.m8n8.x4.shared.b16 {%0,%1,%2,%3}, [%4];"
        : "=r"(r[0]),"=r"(r[1]),"=r"(r[2]),"=r"(r[3]) : "r"(addr));
}
__device__ __forceinline__ void ldm4t(uint32_t* r, uint32_t addr){
    asm volatile("ldmatrix.sync.aligned.m8n8.x4.trans.shared.b16 {%0,%1,%2,%3}, [%4];"
        : "=r"(r[0]),"=r"(r[1]),"=r"(r[2]),"=r"(r[3]) : "r"(addr));
}

// ---------------------------------------------------------------------------
// Fused QKV weight convert + bias pack + count zero (single launch).
// ---------------------------------------------------------------------------
#define QKV_W4 (Dz*QKVN/4)
__global__ __launch_bounds__(256) void cvt_qkv(
    const float* __restrict__ wq, const float* __restrict__ wk,
    const float* __restrict__ wv,
    const float* __restrict__ bq, const float* __restrict__ bk,
    const float* __restrict__ bv,
    __half* __restrict__ out, float* __restrict__ qkvb, int* __restrict__ cnt)
{
    int i = blockIdx.x * 256 + threadIdx.x;
    if (i < QKV_W4) {
        int row = i / (QKVN/4);
        int c4  = (i - row * (QKVN/4)) * 4;
        const float* src;
        float scale = 1.f;
        if (c4 < 512)       { src = wq + (size_t)row*512  + c4;         scale = 0.125f; }
        else if (c4 < 1536) { src = wk + (size_t)row*1024 + (c4-512);  }
        else                { src = wv + (size_t)row*1024 + (c4-1536); }
        float4 a = *(const float4*)src;
        __half2 h0 = __floats2half2_rn(a.x*scale, a.y*scale);
        __half2 h1 = __floats2half2_rn(a.z*scale, a.w*scale);
        uint2 u; u.x = *(uint32_t*)&h0; u.y = *(uint32_t*)&h1;
        *(uint2*)(out + (size_t)row * QKVN + c4) = u;
    } else {
        int j = i - QKV_W4;
        if (j < 512)        qkvb[j] = bq[j] * 0.125f;
        else if (j < 1536)  qkvb[j] = bk[j - 512];
        else if (j < QKVN)  qkvb[j] = bv[j - 1536];
        else if (j < QKVN + Ez) cnt[j - QKVN] = 0;
    }
}

// ---------------------------------------------------------------------------
// Mega convert: wo + gw1 (hi/lo split) + ew1 + ew2 in ONE launch.
// Region-partitioned by flat float4 index.
// ---------------------------------------------------------------------------
#define WO4  (Dz*Dz/4)
#define GW4  (Dz*GHz/4)
#define EW4  ((int)((size_t)Ez*Dz*EDz/4))
#define REST_TOTAL (WO4 + GW4 + 2*EW4)
__global__ __launch_bounds__(256) void cvt_rest(
    const float* __restrict__ wo,  __half* __restrict__ woh,
    const float* __restrict__ gw1, __half* __restrict__ gw1h, __half* __restrict__ gw1l,
    const float* __restrict__ ew1, __half* __restrict__ ew1h,
    const float* __restrict__ ew2, __half* __restrict__ ew2h)
{
    int i = blockIdx.x * 256 + threadIdx.x;
    if (i >= REST_TOTAL) return;
    if (i < WO4) {
        float4 a = ((const float4*)wo)[i];
        __half2 h0 = __floats2half2_rn(a.x, a.y);
        __half2 h1 = __floats2half2_rn(a.z, a.w);
        uint2 u; u.x = *(uint32_t*)&h0; u.y = *(uint32_t*)&h1;
        ((uint2*)woh)[i] = u;
    } else if (i < WO4 + GW4) {
        int k = i - WO4;
        float4 a = ((const float4*)gw1)[k];
        __half hx = __float2half_rn(a.x), hy = __float2half_rn(a.y);
        __half hz = __float2half_rn(a.z), hw = __float2half_rn(a.w);
        __half2 H0; H0.x = hx; H0.y = hy;
        __half2 H1; H1.x = hz; H1.y = hw;
        __half2 L0 = __floats2half2_rn(a.x - __half2float(hx), a.y - __half2float(hy));
        __half2 L1 = __floats2half2_rn(a.z - __half2float(hz), a.w - __half2float(hw));
        uint2 uh; uh.x = *(uint32_t*)&H0; uh.y = *(uint32_t*)&H1;
        uint2 ul; ul.x = *(uint32_t*)&L0; ul.y = *(uint32_t*)&L1;
        ((uint2*)gw1h)[k] = uh;
        ((uint2*)gw1l)[k] = ul;
    } else {
        const float* in; __half* o; int k;
        if (i < WO4 + GW4 + EW4) { in = ew1; o = ew1h; k = i - WO4 - GW4; }
        else                     { in = ew2; o = ew2h; k = i - WO4 - GW4 - EW4; }
        float4 a = ((const float4*)in)[k];
        __half2 h0 = __floats2half2_rn(a.x, a.y);
        __half2 h1 = __floats2half2_rn(a.z, a.w);
        uint2 u; u.x = *(uint32_t*)&h0; u.y = *(uint32_t*)&h1;
        ((uint2*)o)[k] = u;
    }
}

// ---------------------------------------------------------------------------
// LayerNorm: one block per token row of 1024.
// Writes fp16 hi; SPLIT mode additionally writes fp16 lo (x - hi).
// ---------------------------------------------------------------------------
template<bool SPLIT>
__global__ __launch_bounds__(256) void ln_kernel(
    const float* __restrict__ X, const float* __restrict__ g,
    const float* __restrict__ b, __half* __restrict__ O16, __half* __restrict__ OLO)
{
    int t = blockIdx.x;
    int tid = threadIdx.x;
    const float4* x4 = (const float4*)(X + (size_t)t * Dz);
    float4 xv = x4[tid];
    float s  = xv.x + xv.y + xv.z + xv.w;
    float ss = xv.x*xv.x + xv.y*xv.y + xv.z*xv.z + xv.w*xv.w;
    #pragma unroll
    for (int off = 16; off; off >>= 1) {
        s  += __shfl_xor_sync(0xffffffffu, s,  off);
        ss += __shfl_xor_sync(0xffffffffu, ss, off);
    }
    __shared__ float sh_s[8], sh_ss[8];
    if ((tid & 31) == 0) { sh_s[tid >> 5] = s; sh_ss[tid >> 5] = ss; }
    __syncthreads();
    if (tid < 32) {
        float a = (tid < 8) ? sh_s[tid]  : 0.f;
        float c = (tid < 8) ? sh_ss[tid] : 0.f;
        #pragma unroll
        for (int off = 4; off; off >>= 1) {
            a += __shfl_xor_sync(0xffffffffu, a, off);
            c += __shfl_xor_sync(0xffffffffu, c, off);
        }
        if (tid == 0) { sh_s[0] = a; sh_ss[0] = c; }
    }
    __syncthreads();
    float mu  = sh_s[0]  * (1.f / Dz);
    float var = sh_ss[0] * (1.f / Dz) - mu * mu;
    float inv = rsqrtf(var + 1e-5f);
    float4 gv = ((const float4*)g)[tid];
    float4 bv = ((const float4*)b)[tid];
    float4 o;
    o.x = (xv.x - mu) * inv * gv.x + bv.x;
    o.y = (xv.y - mu) * inv * gv.y + bv.y;
    o.z = (xv.z - mu) * inv * gv.z + bv.z;
    o.w = (xv.w - mu) * inv * gv.w + bv.w;
    __half hx = __float2half_rn(o.x), hy = __float2half_rn(o.y);
    __half hz = __float2half_rn(o.z), hw = __float2half_rn(o.w);
    __half2 p0; p0.x = hx; p0.y = hy;
    __half2 p1; p1.x = hz; p1.y = hw;
    uint2 u; u.x = *(uint32_t*)&p0; u.y = *(uint32_t*)&p1;
    ((uint2*)(O16 + (size_t)t * Dz))[tid] = u;
    if (SPLIT) {
        __half2 l0 = __floats2half2_rn(o.x - __half2float(hx), o.y - __half2float(hy));
        __half2 l1 = __floats2half2_rn(o.z - __half2float(hz), o.w - __half2float(hw));
        uint2 ul; ul.x = *(uint32_t*)&l0; ul.y = *(uint32_t*)&l1;
        ((uint2*)(OLO + (size_t)t * Dz))[tid] = ul;
    }
}

// ---------------------------------------------------------------------------
// fp16 tensor-core GEMM: C[M,N] = act(A @ B + bias)(+resid).
// GMODE: 0 dense; 2 A gathered via elist (>>ashift), C dense at e*Tz+m;
//        3 A dense at e*Tz+m, C scattered via elist.
// BM=128, BN=128, BK=64 halves, 256 threads, warp 64x32, 3-stage cp.async.
// Single __syncthreads per k-tile (trailing barrier redundant).
// ---------------------------------------------------------------------------
#define GEMMH_SMEM (3*128*72*2 + 3*64*136*2)
template<int ACT, int GMODE, bool RESID, bool OUTH>
__global__ void __launch_bounds__(256,2) gemm_hc(
    const __half* __restrict__ A, const __half* __restrict__ B,
    const float* __restrict__ bias, void* __restrict__ Cv,
    int M, int N, int K,
    const float* __restrict__ resid,
    const int* __restrict__ elist, const int* __restrict__ cnt, int ashift)
{
    extern __shared__ __half smh[];
    __half* As = smh;                  // [3][128][72]
    __half* Bs = smh + 3*128*72;       // [3][64][136]

    int e = blockIdx.z;
    const __half* Bp = B + (size_t)e * K * N;
    const float*  bp = bias + (size_t)e * N;
    int mcount = (GMODE != 0) ? cnt[e] : M;
    int m0 = blockIdx.y * 128;
    if (m0 >= mcount) return;
    int n0 = blockIdx.x * 128;
    const int* lst = (GMODE != 0) ? (elist + e * Tz) : (const int*)nullptr;

    int tid = threadIdx.x;
    int lane = tid & 31, wid = tid >> 5;
    int warpM = wid >> 2, warpN = wid & 3;

    int aq = (tid & 7) * 8;
    const __half* aptr[4];
    bool aval[4];
    uint32_t adst[4];
    #pragma unroll
    for (int i = 0; i < 4; i++) {
        int r = (tid >> 3) + 32 * i;
        int m = m0 + r;
        bool v = (m < mcount);
        size_t rowg;
        if (GMODE == 2)      rowg = v ? (size_t)(lst[m] >> ashift) : 0;
        else if (GMODE == 3) rowg = v ? (size_t)(e * Tz + m) : 0;
        else                 rowg = v ? (size_t)m : 0;
        aptr[i] = A + rowg * (size_t)K + aq;
        aval[i] = v;
        adst[i] = s2u(&As[r * 72 + aq]);
    }
    int brow = tid >> 2, bq = (tid & 3) * 32;
    const __half* bptr = Bp + (size_t)brow * N + n0 + bq;
    uint32_t bdst = s2u(&Bs[brow * 136 + bq]);
    const uint32_t abuf = 128*72*2, bbuf = 64*136*2;

    uint32_t as_u = s2u(As), bs_u = s2u(Bs);

    float acc[4][4][4];
    #pragma unroll
    for (int i=0;i<4;i++)
        #pragma unroll
        for (int j=0;j<4;j++)
            #pragma unroll
            for (int l=0;l<4;l++) acc[i][j][l] = 0.f;

    int KT = K / 64;

    auto stageTile = [&](int kt2, int buf){
        int k0 = kt2 * 64;
        #pragma unroll
        for (int i=0;i<4;i++) cpa16(adst[i] + buf*abuf, aptr[i] + k0, aval[i]);
        #pragma unroll
        for (int j=0;j<4;j++) cpa16(bdst + buf*bbuf + j*16,
                                    bptr + (size_t)k0*N + j*8, true);
    };

    stageTile(0, 0); cp_commit();
    if (KT > 1) stageTile(1, 1);
    cp_commit();

    int bufc = 0, bufs = 2;
    uint32_t lr = lane & 15, lc = (lane >> 4) * 8;
    for (int kt = 0; kt < KT; kt++) {
        cp_wait1();
        __syncthreads();
        if (kt + 2 < KT) stageTile(kt+2, bufs);
        cp_commit();

        uint32_t abase = as_u + ((uint32_t)bufc*(128*72) + (warpM*64 + lr)*72 + lc)*2;
        uint32_t bbase = bs_u + ((uint32_t)bufc*(64*136) + lr*136 + warpN*32 + lc)*2;
        #pragma unroll
        for (int ks = 0; ks < 4; ks++) {
            uint32_t ah[4][4];
            #pragma unroll
            for (int mt = 0; mt < 4; mt++)
                ldm4(ah[mt], abase + (mt*16*72 + ks*16)*2);
            uint32_t bt[2][4];
            #pragma unroll
            for (int pr = 0; pr < 2; pr++)
                ldm4t(bt[pr], bbase + (ks*16*136 + pr*16)*2);
            #pragma unroll
            for (int mt = 0; mt < 4; mt++) {
                mma16(acc[mt][0], ah[mt], bt[0][0], bt[0][1]);
                mma16(acc[mt][1], ah[mt], bt[0][2], bt[0][3]);
                mma16(acc[mt][2], ah[mt], bt[1][0], bt[1][1]);
                mma16(acc[mt][3], ah[mt], bt[1][2], bt[1][3]);
            }
        }
        bufc = (bufc == 2) ? 0 : bufc + 1;
        bufs = (bufs == 2) ? 0 : bufs + 1;
    }

    float2 bv[4];
    #pragma unroll
    for (int nt = 0; nt < 4; nt++)
        bv[nt] = *(const float2*)(bp + n0 + warpN*32 + (lane&3)*2 + nt*8);

    float*  Cf = (float*)Cv;
    __half* Ch = (__half*)Cv;
    #pragma unroll
    for (int mt = 0; mt < 4; mt++) {
        #pragma unroll
        for (int hf = 0; hf < 2; hf++) {
            int r = m0 + warpM*64 + mt*16 + (lane>>2) + hf*8;
            if (r >= mcount) continue;
            size_t crow;
            if (GMODE == 2)      crow = (size_t)(e * Tz + r);
            else if (GMODE == 3) crow = (size_t)lst[r];
            else                 crow = (size_t)r;
            int coff = n0 + warpN*32 + (lane&3)*2;
            const float* Rr = RESID ? (resid + crow*(size_t)N + coff) : (const float*)nullptr;
            #pragma unroll
            for (int nt = 0; nt < 4; nt++) {
                float v0 = acc[mt][nt][hf*2+0] + bv[nt].x;
                float v1 = acc[mt][nt][hf*2+1] + bv[nt].y;
                if (ACT == 1) { v0 = fmaxf(v0, 0.f); v1 = fmaxf(v1, 0.f); }
                if (ACT == 2) {
                    v0 = 0.5f*v0*(1.f + erff(v0*0.70710678118654752f));
                    v1 = 0.5f*v1*(1.f + erff(v1*0.70710678118654752f));
                }
                if (RESID) { v0 += Rr[nt*8]; v1 += Rr[nt*8+1]; }
                if (OUTH) {
                    __half2 h = __floats2half2_rn(v0, v1);
                    *(__half2*)(Ch + crow*(size_t)N + coff + nt*8) = h;
                } else {
                    float2 o; o.x = v0; o.y = v1;
                    *(float2*)(Cf + crow*(size_t)N + coff + nt*8) = o;
                }
            }
        }
    }
}

// ---------------------------------------------------------------------------
// Split-fp16 gate GEMM (near-fp32): gh = relu((Ah+Al)@(Bh+Bl) + bias)
//   = Ah@Bh + Al@Bh + Ah@Bl (Al@Bl dropped, ~2^-22 relative).
// Single __syncthreads per k-tile.
// ---------------------------------------------------------------------------
#define GATE_SMEM (2*2*128*40*2 + 2*2*32*136*2)
__global__ void __launch_bounds__(256,2) gemm_gate16(
    const __half* __restrict__ Ah, const __half* __restrict__ Al,
    const __half* __restrict__ Bh, const __half* __restrict__ Bl,
    const float* __restrict__ bias, float* __restrict__ C,
    int M, int N, int K)
{
    extern __shared__ __half smh[];
    __half* Ahs = smh;                        // [2][128][40]
    __half* Als = Ahs + 2*128*40;             // [2][128][40]
    __half* Bhs = Als + 2*128*40;             // [2][32][136]
    __half* Bls = Bhs + 2*32*136;             // [2][32][136]

    int m0 = blockIdx.y * 128;
    int n0 = blockIdx.x * 128;
    int tid = threadIdx.x;
    int lane = tid & 31, wid = tid >> 5;
    int warpM = wid >> 2, warpN = wid & 3;

    int arow = tid >> 1, acol = (tid & 1) * 16;
    const __half* ahp = Ah + (size_t)(m0 + arow) * K + acol;
    const __half* alp = Al + (size_t)(m0 + arow) * K + acol;
    uint32_t ahd = s2u(&Ahs[arow * 40 + acol]);
    uint32_t ald = s2u(&Als[arow * 40 + acol]);
    int brow = tid >> 3, bcol = (tid & 7) * 16;
    const __half* bhp = Bh + (size_t)brow * N + n0 + bcol;
    const __half* blp = Bl + (size_t)brow * N + n0 + bcol;
    uint32_t bhd = s2u(&Bhs[brow * 136 + bcol]);
    uint32_t bld = s2u(&Bls[brow * 136 + bcol]);

    const uint32_t abuf = 128*40*2, bbuf = 32*136*2;

    auto stage = [&](int kt, int buf){
        int k0 = kt * 32;
        cpa16(ahd + buf*abuf,      ahp + k0, true);
        cpa16(ahd + buf*abuf + 16, ahp + k0 + 8, true);
        cpa16(ald + buf*abuf,      alp + k0, true);
        cpa16(ald + buf*abuf + 16, alp + k0 + 8, true);
        cpa16(bhd + buf*bbuf,      bhp + (size_t)k0*N, true);
        cpa16(bhd + buf*bbuf + 16, bhp + (size_t)k0*N + 8, true);
        cpa16(bld + buf*bbuf,      blp + (size_t)k0*N, true);
        cpa16(bld + buf*bbuf + 16, blp + (size_t)k0*N + 8, true);
    };

    uint32_t ahs_u = s2u(Ahs), als_u = s2u(Als);
    uint32_t bhs_u = s2u(Bhs), bls_u = s2u(Bls);

    float acc[4][4][4];
    #pragma unroll
    for (int i=0;i<4;i++)
        #pragma unroll
        for (int j=0;j<4;j++)
            #pragma unroll
            for (int l=0;l<4;l++) acc[i][j][l] = 0.f;

    int KT = K / 32;
    stage(0, 0); cp_commit();

    uint32_t lr = lane & 15, lc = (lane >> 4) * 8;
    for (int kt = 0; kt < KT; kt++) {
        int buf = kt & 1;
        cp_wait0();
        __syncthreads();
        if (kt + 1 < KT) { stage(kt+1, buf ^ 1); }
        cp_commit();

        uint32_t aoff = ((uint32_t)buf*(128*40) + (warpM*64 + lr)*40 + lc)*2;
        uint32_t boff = ((uint32_t)buf*(32*136) + lr*136 + warpN*32 + lc)*2;
        #pragma unroll
        for (int ks = 0; ks < 2; ks++) {
            uint32_t ah[4][4], al[4][4];
            #pragma unroll
            for (int mt = 0; mt < 4; mt++) {
                ldm4(ah[mt], ahs_u + aoff + (mt*16*40 + ks*16)*2);
                ldm4(al[mt], als_u + aoff + (mt*16*40 + ks*16)*2);
            }
            uint32_t bth[2][4], btl[2][4];
            #pragma unroll
            for (int pr = 0; pr < 2; pr++) {
                ldm4t(bth[pr], bhs_u + boff + (ks*16*136 + pr*16)*2);
                ldm4t(btl[pr], bls_u + boff + (ks*16*136 + pr*16)*2);
            }
            #pragma unroll
            for (int mt = 0; mt < 4; mt++) {
                mma16(acc[mt][0], ah[mt], bth[0][0], bth[0][1]);
                mma16(acc[mt][1], ah[mt], bth[0][2], bth[0][3]);
                mma16(acc[mt][2], ah[mt], bth[1][0], bth[1][1]);
                mma16(acc[mt][3], ah[mt], bth[1][2], bth[1][3]);
                mma16(acc[mt][0], al[mt], bth[0][0], bth[0][1]);
                mma16(acc[mt][1], al[mt], bth[0][2], bth[0][3]);
                mma16(acc[mt][2], al[mt], bth[1][0], bth[1][1]);
                mma16(acc[mt][3], al[mt], bth[1][2], bth[1][3]);
                mma16(acc[mt][0], ah[mt], btl[0][0], btl[0][1]);
                mma16(acc[mt][1], ah[mt], btl[0][2], btl[0][3]);
                mma16(acc[mt][2], ah[mt], btl[1][0], btl[1][1]);
                mma16(acc[mt][3], ah[mt], btl[1][2], btl[1][3]);
            }
        }
    }

    float2 bv[4];
    #pragma unroll
    for (int nt = 0; nt < 4; nt++)
        bv[nt] = *(const float2*)(bias + n0 + warpN*32 + (lane&3)*2 + nt*8);

    #pragma unroll
    for (int mt = 0; mt < 4; mt++)
        #pragma unroll
        for (int hf = 0; hf < 2; hf++) {
            int r = m0 + warpM*64 + mt*16 + (lane>>2) + hf*8;
            float* Cr = C + (size_t)r*N + n0 + warpN*32 + (lane&3)*2;
            #pragma unroll
            for (int nt = 0; nt < 4; nt++) {
                float v0 = fmaxf(acc[mt][nt][hf*2+0] + bv[nt].x, 0.f);
                float v1 = fmaxf(acc[mt][nt][hf*2+1] + bv[nt].y, 0.f);
                float2 o; o.x = v0; o.y = v1;
                *(float2*)(Cr + nt*8) = o;
            }
        }
}

// ---------------------------------------------------------------------------
// Fused flash attention, fp16 mma.sync, online softmax (fp32 stats).
// ---------------------------------------------------------------------------
#define FA_SMEM (128*136*2 + 4*128*72*2)
__global__ void __launch_bounds__(256,2) fa_h(
    const __half* __restrict__ QKV, __half* __restrict__ O)
{
    extern __shared__ __half smh[];
    __half* Ps  = smh;                     // [128][136]; alias Qs [128][72]
    __half* Ks0 = smh + 128*136;
    __half* Ks1 = Ks0 + 128*72;
    __half* Vs0 = Ks1 + 128*72;
    __half* Vs1 = Vs0 + 128*72;

    int bh = blockIdx.y, b = bh >> 4, h = bh & 15, g = h >> 1;
    int q0 = blockIdx.x * 128;
    int tid = threadIdx.x, lane = tid & 31, w = tid >> 5;

    const __half* Qb = QKV + (size_t)(b*Sz + q0) * QKVN + g*64;
    {
        int row = tid >> 1;
        #pragma unroll
        for (int j = 0; j < 4; j++) {
            int c = (tid & 1) + 2*j;
            cpa16(s2u(Ps + row*72 + c*8), Qb + (size_t)row*QKVN + c*8, true);
        }
    }
    cp_commit();

    const __half* Kb = QKV + (size_t)(b*Sz)*QKVN + 512 + h*64;
    const __half* Vb = QKV + (size_t)(b*Sz)*QKVN + 1536 + h*64;

    auto stageKV = [&](int kt, int buf){
        int row = tid >> 1;
        __half* Kd = (buf ? Ks1 : Ks0) + row*72;
        __half* Vd = (buf ? Vs1 : Vs0) + row*72;
        const __half* kp = Kb + (size_t)(kt*128 + row)*QKVN;
        const __half* vp = Vb + (size_t)(kt*128 + row)*QKVN;
        #pragma unroll
        for (int j = 0; j < 4; j++) {
            int c = (tid & 1) + 2*j;
            cpa16(s2u(Kd + c*8), kp + c*8, true);
            cpa16(s2u(Vd + c*8), vp + c*8, true);
        }
    };
    stageKV(0, 0); cp_commit();

    asm volatile("cp.async.wait_group 1;\n");
    __syncthreads();
    uint32_t lr = lane & 15, lc = (lane >> 4) * 8;
    uint32_t qbase = s2u(Ps) + ((w*16 + lr)*72 + lc)*2;
    uint32_t qf[4][4];
    #pragma unroll
    for (int ks = 0; ks < 4; ks++) ldm4(qf[ks], qbase + ks*32);
    __syncthreads();

    float m0 = -INFINITY, m1 = -INFINITY, l0 = 0.f, l1 = 0.f;
    float oacc[8][4];
    #pragma unroll
    for (int i=0;i<8;i++)
        #pragma unroll
        for (int j=0;j<4;j++) oacc[i][j] = 0.f;

    uint32_t pabase = s2u(Ps) + ((w*16 + lr)*136 + lc)*2;
    __half* prow = Ps + (size_t)(w*16 + (lane>>2))*136 + (lane&3)*2;

    for (int kt = 0; kt < 8; kt++) {
        int buf = kt & 1;
        cp_wait0();
        __syncthreads();
        if (kt + 1 < 8) stageKV(kt+1, buf ^ 1);
        cp_commit();

        float sacc[16][4];
        #pragma unroll
        for (int i=0;i<16;i++)
            #pragma unroll
            for (int j=0;j<4;j++) sacc[i][j] = 0.f;
        uint32_t kbase = s2u(buf ? Ks1 : Ks0) + (lr*72 + lc)*2;
        #pragma unroll
        for (int ks = 0; ks < 4; ks++) {
            #pragma unroll
            for (int np = 0; np < 8; np++) {
                uint32_t r[4];
                ldm4(r, kbase + (np*16*72 + ks*16)*2);
                mma16(sacc[2*np  ], qf[ks], r[0], r[2]);
                mma16(sacc[2*np+1], qf[ks], r[1], r[3]);
            }
        }

        float t0 = -INFINITY, t1 = -INFINITY;
        #pragma unroll
        for (int nt = 0; nt < 16; nt++) {
            t0 = fmaxf(t0, fmaxf(sacc[nt][0], sacc[nt][1]));
            t1 = fmaxf(t1, fmaxf(sacc[nt][2], sacc[nt][3]));
        }
        t0 = fmaxf(t0, __shfl_xor_sync(0xffffffffu, t0, 1));
        t0 = fmaxf(t0, __shfl_xor_sync(0xffffffffu, t0, 2));
        t1 = fmaxf(t1, __shfl_xor_sync(0xffffffffu, t1, 1));
        t1 = fmaxf(t1, __shfl_xor_sync(0xffffffffu, t1, 2));
        float mn0 = fmaxf(m0, t0), mn1 = fmaxf(m1, t1);
        float sc0 = __expf(m0 - mn0), sc1 = __expf(m1 - mn1);
        float s0 = 0.f, s1 = 0.f;
        #pragma unroll
        for (int nt = 0; nt < 16; nt++) {
            sacc[nt][0] = __expf(sacc[nt][0] - mn0);
            sacc[nt][1] = __expf(sacc[nt][1] - mn0);
            sacc[nt][2] = __expf(sacc[nt][2] - mn1);
            sacc[nt][3] = __expf(sacc[nt][3] - mn1);
            s0 += sacc[nt][0] + sacc[nt][1];
            s1 += sacc[nt][2] + sacc[nt][3];
        }
        s0 += __shfl_xor_sync(0xffffffffu, s0, 1);
        s0 += __shfl_xor_sync(0xffffffffu, s0, 2);
        s1 += __shfl_xor_sync(0xffffffffu, s1, 1);
        s1 += __shfl_xor_sync(0xffffffffu, s1, 2);
        l0 = l0*sc0 + s0; l1 = l1*sc1 + s1;
        m0 = mn0; m1 = mn1;
        #pragma unroll
        for (int nt = 0; nt < 8; nt++) {
            oacc[nt][0] *= sc0; oacc[nt][1] *= sc0;
            oacc[nt][2] *= sc1; oacc[nt][3] *= sc1;
        }

        #pragma unroll
        for (int nt = 0; nt < 16; nt++) {
            *(__half2*)(prow + nt*8)          = __floats2half2_rn(sacc[nt][0], sacc[nt][1]);
            *(__half2*)(prow + 8*136 + nt*8)  = __floats2half2_rn(sacc[nt][2], sacc[nt][3]);
        }
        __syncwarp();

        uint32_t vbase = s2u(buf ? Vs1 : Vs0) + (lr*72 + lc)*2;
        #pragma unroll
        for (int k2 = 0; k2 < 8; k2++) {
            uint32_t pf[4];
            ldm4(pf, pabase + k2*32);
            #pragma unroll
            for (int hp = 0; hp < 4; hp++) {
                uint32_t vt[4];
                ldm4t(vt, vbase + (k2*16*72 + hp*16)*2);
                mma16(oacc[2*hp  ], pf, vt[0], vt[1]);
                mma16(oacc[2*hp+1], pf, vt[2], vt[3]);
            }
        }
    }

    float i0 = 1.f / l0, i1 = 1.f / l1;
    int r0 = q0 + w*16 + (lane >> 2);
    __half* Op = O + (size_t)(b*Sz + r0)*1024 + h*64 + (lane&3)*2;
    #pragma unroll
    for (int nt = 0; nt < 8; nt++) {
        *(__half2*)(Op + nt*8)          = __floats2half2_rn(oacc[nt][0]*i0, oacc[nt][1]*i0);
        *(__half2*)(Op + 8*1024 + nt*8) = __floats2half2_rn(oacc[nt][2]*i1, oacc[nt][3]*i1);
    }
}

// ---------------------------------------------------------------------------
// Gate head + softmax + top-2 + renorm + routing. One warp per token.
// ---------------------------------------------------------------------------
__global__ __launch_bounds__(256) void gate_route_kernel(
    const float* __restrict__ GH, const float* __restrict__ gw2,
    const float* __restrict__ gb2,
    float* __restrict__ wout, int* __restrict__ cnt, int* __restrict__ elist)
{
    int warp = threadIdx.x >> 5;
    int lane = threadIdx.x & 31;
    int t = blockIdx.x * 8 + warp;
    if (t >= Tz) return;

    float logit[Ez];
    #pragma unroll
    for (int o = 0; o < Ez; o++) {
        float s = 0.f;
        for (int i = lane; i < GHz; i += 32)
            s += GH[(size_t)t * GHz + i] * gw2[(size_t)i * Ez + o];
        #pragma unroll
        for (int off = 16; off; off >>= 1)
            s += __shfl_xor_sync(0xffffffffu, s, off);
        logit[o] = s + gb2[o];
    }
    if (lane == 0) {
        float m = logit[0];
        #pragma unroll
        for (int o = 1; o < Ez; o++) m = fmaxf(m, logit[o]);
        float w[Ez], sum = 0.f;
        #pragma unroll
        for (int o = 0; o < Ez; o++) { w[o] = expf(logit[o] - m); sum += w[o]; }
        float invs = 1.f / sum;
        #pragma unroll
        for (int o = 0; o < Ez; o++) w[o] *= invs;
        int i0 = 0; float v0 = w[0];
        #pragma unroll
        for (int o = 1; o < Ez; o++) if (w[o] > v0) { v0 = w[o]; i0 = o; }
        int i1 = -1; float v1 = -1.f;
        #pragma unroll
        for (int o = 0; o < Ez; o++)
            if (o != i0 && w[o] > v1) { v1 = w[o]; i1 = o; }
        float e1 = expf(v1 - v0);
        float den = 1.f + e1;
        wout[2*t + 0] = 1.f / den;
        wout[2*t + 1] = e1 / den;
        int p0 = atomicAdd(&cnt[i0], 1);
        elist[i0 * Tz + p0] = 2*t + 0;
        int p1 = atomicAdd(&cnt[i1], 1);
        elist[i1 * Tz + p1] = 2*t + 1;
    }
}

// ---------------------------------------------------------------------------
// Final combine: out = x1 + w0*eo[2t] + w1*eo[2t+1]  (eo fp16)
// ---------------------------------------------------------------------------
__global__ __launch_bounds__(256) void combine_kernel(
    const float* __restrict__ x1, const __half* __restrict__ eo,
    const float* __restrict__ w, float* __restrict__ out)
{
    int idx = blockIdx.x * 256 + threadIdx.x;
    int t = idx >> 8;
    int c = idx & 255;
    float w0 = w[2*t], w1 = w[2*t + 1];
    float4 a  = ((const float4*)x1)[idx];
    uint2 u0 = ((const uint2*)(eo + (size_t)(2*t)     * Dz))[c];
    uint2 u1 = ((const uint2*)(eo + (size_t)(2*t + 1) * Dz))[c];
    float2 e0a = __half22float2(*(__half2*)&u0.x);
    float2 e0b = __half22float2(*(__half2*)&u0.y);
    float2 e1a = __half22float2(*(__half2*)&u1.x);
    float2 e1b = __half22float2(*(__half2*)&u1.y);
    float4 r;
    r.x = a.x + w0 * e0a.x + w1 * e1a.x;
    r.y = a.y + w0 * e0a.y + w1 * e1a.y;
    r.z = a.z + w0 * e0b.x + w1 * e1b.x;
    r.w = a.w + w0 * e0b.y + w1 * e1b.y;
    ((float4*)out)[idx] = r;
}

// ---------------------------------------------------------------------------
// Host launch (single stream — graph-capture safe)
// ---------------------------------------------------------------------------
extern "C" void kernel_launch(void* const* d_in, const int* in_sizes, int n_in,
                              void* d_out, int out_size)
{
    const float* x    = (const float*)d_in[0];
    const float* wq   = (const float*)d_in[1];
    const float* bq   = (const float*)d_in[2];
    const float* wk   = (const float*)d_in[3];
    const float* bk   = (const float*)d_in[4];
    const float* wv   = (const float*)d_in[5];
    const float* bv   = (const float*)d_in[6];
    const float* wo   = (const float*)d_in[7];
    const float* bo   = (const float*)d_in[8];
    const float* ln1g = (const float*)d_in[9];
    const float* ln1b = (const float*)d_in[10];
    const float* ln2g = (const float*)d_in[11];
    const float* ln2b = (const float*)d_in[12];
    const float* gw1  = (const float*)d_in[13];
    const float* gb1  = (const float*)d_in[14];
    const float* gw2  = (const float*)d_in[15];
    const float* gb2  = (const float*)d_in[16];
    const float* ew1  = (const float*)d_in[17];
    const float* eb1  = (const float*)d_in[18];
    const float* ew2  = (const float*)d_in[19];
    const float* eb2  = (const float*)d_in[20];
    float* out = (float*)d_out;

    __half *h1h, *qkvh, *aoh, *h2h, *h2l, *hidh, *eo;
    __half *wqkvh, *woh, *ew1h, *ew2h, *gw1h, *gw1l;
    float *x1, *gh, *w, *qkvb;
    int *cnt, *elist;
    cudaGetSymbolAddress((void**)&h1h,  g_h1h);
    cudaGetSymbolAddress((void**)&qkvh, g_qkvh);
    cudaGetSymbolAddress((void**)&aoh,  g_aoh);
    cudaGetSymbolAddress((void**)&x1,   g_x1);
    cudaGetSymbolAddress((void**)&h2h,  g_h2h);
    cudaGetSymbolAddress((void**)&h2l,  g_h2l);
    cudaGetSymbolAddress((void**)&gh,   g_gh);
    cudaGetSymbolAddress((void**)&w,    g_w);
    cudaGetSymbolAddress((void**)&hidh, g_hidh);
    cudaGetSymbolAddress((void**)&eo,   g_eo);
    cudaGetSymbolAddress((void**)&cnt,  g_cnt);
    cudaGetSymbolAddress((void**)&elist,g_elist);
    cudaGetSymbolAddress((void**)&wqkvh,g_wqkvh);
    cudaGetSymbolAddress((void**)&woh,  g_woh);
    cudaGetSymbolAddress((void**)&ew1h, g_ew1h);
    cudaGetSymbolAddress((void**)&ew2h, g_ew2h);
    cudaGetSymbolAddress((void**)&gw1h, g_gw1h);
    cudaGetSymbolAddress((void**)&gw1l, g_gw1l);
    cudaGetSymbolAddress((void**)&qkvb, g_qkvb);

    cudaFuncSetAttribute(gemm_hc<0,0,false,true>, cudaFuncAttributeMaxDynamicSharedMemorySize, GEMMH_SMEM);
    cudaFuncSetAttribute(gemm_hc<0,0,true,false>, cudaFuncAttributeMaxDynamicSharedMemorySize, GEMMH_SMEM);
    cudaFuncSetAttribute(gemm_hc<2,2,false,true>, cudaFuncAttributeMaxDynamicSharedMemorySize, GEMMH_SMEM);
    cudaFuncSetAttribute(gemm_hc<0,3,false,true>, cudaFuncAttributeMaxDynamicSharedMemorySize, GEMMH_SMEM);
    cudaFuncSetAttribute(gemm_gate16, cudaFuncAttributeMaxDynamicSharedMemorySize, GATE_SMEM);
    cudaFuncSetAttribute(fa_h, cudaFuncAttributeMaxDynamicSharedMemorySize, FA_SMEM);

    // launch 0: fused qkv weight convert + bias pack + count zero
    cvt_qkv<<<(QKV_W4 + QKVN + Ez + 255)/256, 256>>>(
        wq, wk, wv, bq, bk, bv, wqkvh, qkvb, cnt);
    // launch 1: all remaining weight converts in one HBM-bound pass
    cvt_rest<<<(REST_TOTAL + 255)/256, 256>>>(
        wo, woh, gw1, gw1h, gw1l, ew1, ew1h, ew2, ew2h);

    // LN1
    ln_kernel<false><<<Tz, 256>>>(x, ln1g, ln1b, h1h, nullptr);

    // Fused QKV projection
    gemm_hc<0,0,false,true><<<dim3(QKVN/128, 32, 1), 256, GEMMH_SMEM>>>(
        h1h, wqkvh, qkvb, qkvh, Tz, QKVN, Dz, nullptr, nullptr, nullptr, 0);

    fa_h<<<dim3(Sz/128, Bz*Hh), 256, FA_SMEM>>>(qkvh, aoh);

    // Output projection + residual -> x1 fp32
    gemm_hc<0,0,true,false><<<dim3(8, 32, 1), 256, GEMMH_SMEM>>>(
        aoh, woh, bo, x1, Tz, Dz, Dz, x, nullptr, nullptr, 0);

    ln_kernel<true><<<Tz, 256>>>(x1, ln2g, ln2b, h2h, h2l);

    gemm_gate16<<<dim3(GHz/128, Tz/128, 1), 256, GATE_SMEM>>>(
        h2h, h2l, gw1h, gw1l, gb1, gh, Tz, GHz, Dz);

    gate_route_kernel<<<Tz/8, 256>>>(gh, gw2, gb2, w, cnt, elist);

    // Expert FFN: GEMM1 A-gathered / C-dense (hid rows e*Tz+m),
    //             GEMM2 A-dense / C-scattered (eo rows = assignment id)
    gemm_hc<2,2,false,true><<<dim3(EDz/128, Tz/128, Ez), 256, GEMMH_SMEM>>>(
        h2h, ew1h, eb1, hidh, Tz, EDz, Dz, nullptr, elist, cnt, 1);
    gemm_hc<0,3,false,true><<<dim3(Dz/128, Tz/128, Ez), 256, GEMMH_SMEM>>>(
        hidh, ew2h, eb2, eo, Tz, Dz, EDz, nullptr, elist, cnt, 0);

    combine_kernel<<<(Tz*Dz/4)/256, 256>>>(x1, eo, w, out);
}

// round 14
// speedup vs baseline: 1.0161x; 1.0161x over previous
#include <cuda_runtime.h>
#include <cuda_fp16.h>
#include <math.h>
#include <stdint.h>

// ---------------------------------------------------------------------------
// Problem constants
// ---------------------------------------------------------------------------
#define Bz   4
#define Sz   1024
#define Dz   1024
#define Hh   16
#define Gg   8
#define HDz  64
#define Ez   8
#define EDz  2048
#define GHz  512
#define Tz   (Bz*Sz)          // 4096 tokens
#define QKVN 2560             // packed q(512) | k(1024) | v(1024)

// ---------------------------------------------------------------------------
// Scratch (static device memory)
// ---------------------------------------------------------------------------
__device__ __half g_h1h [Tz*Dz];
__device__ __half g_qkvh[(size_t)Tz*QKVN];
__device__ __half g_aoh [Tz*Dz];
__device__ float  g_x1  [Tz*Dz];
__device__ __half g_h2h [Tz*Dz];       // LN2 out, fp16 hi
__device__ __half g_h2l [Tz*Dz];       // LN2 out, fp16 lo (residual)
__device__ float  g_gh  [Tz*GHz];
__device__ float  g_w   [Tz*2];
__device__ int    g_cnt [Ez];
__device__ int    g_elist[Ez*Tz];
__device__ __half g_hidh[(size_t)Ez*Tz*EDz];   // per-expert dense rows (e*Tz + m)
__device__ __half g_eo  [(size_t)Tz*2*Dz];
// fp16 weights ([K][N] row-major; qkv packed) + packed qkv bias
__device__ __half g_wqkvh[(size_t)Dz*QKVN];
__device__ __half g_woh  [(size_t)Dz*Dz];
__device__ __half g_ew1h [(size_t)Ez*Dz*EDz];
__device__ __half g_ew2h [(size_t)Ez*EDz*Dz];
__device__ __half g_gw1h [(size_t)Dz*GHz];   // gate w1 hi
__device__ __half g_gw1l [(size_t)Dz*GHz];   // gate w1 lo
__device__ float  g_qkvb [QKVN];

// ---------------------------------------------------------------------------
// Helpers
// ---------------------------------------------------------------------------
__device__ __forceinline__ uint32_t s2u(const void* p){
    return (uint32_t)__cvta_generic_to_shared(p);
}
__device__ __forceinline__ void cpa16(uint32_t d, const void* s, bool v){
    asm volatile("cp.async.cg.shared.global [%0], [%1], 16, %2;\n"
                 :: "r"(d), "l"(s), "r"(v ? 16 : 0));
}
__device__ __forceinline__ void cp_commit(){ asm volatile("cp.async.commit_group;\n"); }
__device__ __forceinline__ void cp_wait0(){ asm volatile("cp.async.wait_group 0;\n"); }
// Bulk async copy global->shared, completion via mbarrier tx-bytes
__device__ __forceinline__ void cpbulk(uint32_t d, const void* s, uint32_t bytes, uint32_t mbar){
    asm volatile("cp.async.bulk.shared::cluster.global.mbarrier::complete_tx::bytes "
                 "[%0], [%1], %2, [%3];"
                 :: "r"(d), "l"(s), "r"(bytes), "r"(mbar) : "memory");
}
__device__ __forceinline__ void mbar_init(uint32_t mbar, uint32_t cnt){
    asm volatile("mbarrier.init.shared.b64 [%0], %1;" :: "r"(mbar), "r"(cnt) : "memory");
}
__device__ __forceinline__ void mbar_expect(uint32_t mbar, uint32_t bytes){
    asm volatile("mbarrier.arrive.expect_tx.shared.b64 _, [%0], %1;"
                 :: "r"(mbar), "r"(bytes) : "memory");
}
__device__ __forceinline__ void mbar_arrive(uint32_t mbar){
    asm volatile("mbarrier.arrive.shared.b64 _, [%0];" :: "r"(mbar) : "memory");
}
__device__ __forceinline__ void mbar_wait(uint32_t mbar, uint32_t parity){
    asm volatile(
        "{\n\t.reg .pred P1;\n"
        "LW%=:\n\t"
        "mbarrier.try_wait.parity.acquire.cta.shared::cta.b64 P1, [%0], %1, 0x989680;\n\t"
        "@P1 bra LD%=;\n\t"
        "bra LW%=;\n"
        "LD%=:\n\t}"
        :: "r"(mbar), "r"(parity) : "memory");
}
__device__ __forceinline__ void mma16(float* c, const uint32_t* a, uint32_t b0, uint32_t b1){
    asm volatile("mma.sync.aligned.m16n8k16.row.col.f32.f16.f16.f32 "
        "{%0,%1,%2,%3},{%4,%5,%6,%7},{%8,%9},{%0,%1,%2,%3};\n"
        : "+f"(c[0]),"+f"(c[1]),"+f"(c[2]),"+f"(c[3])
        : "r"(a[0]),"r"(a[1]),"r"(a[2]),"r"(a[3]),"r"(b0),"r"(b1));
}
__device__ __forceinline__ void ldm4(uint32_t* r, uint32_t addr){
    asm volatile("ldmatrix.sync.aligned.m8n8.x4.shared.b16 {%0,%1,%2,%3}, [%4];"
        : "=r"(r[0]),"=r"(r[1]),"=r"(r[2]),"=r"(r[3]) : "r"(addr));
}
__device__ __forceinline__ void ldm4t(uint32_t* r, uint32_t addr){
    asm volatile("ldmatrix.sync.aligned.m8n8.x4.trans.shared.b16 {%0,%1,%2,%3}, [%4];"
        : "=r"(r[0]),"=r"(r[1]),"=r"(r[2]),"=r"(r[3]) : "r"(addr));
}

// ---------------------------------------------------------------------------
// Fused QKV weight convert + bias pack + count zero (single launch).
// ---------------------------------------------------------------------------
#define QKV_W4 (Dz*QKVN/4)
__global__ __launch_bounds__(256) void cvt_qkv(
    const float* __restrict__ wq, const float* __restrict__ wk,
    const float* __restrict__ wv,
    const float* __restrict__ bq, const float* __restrict__ bk,
    const float* __restrict__ bv,
    __half* __restrict__ out, float* __restrict__ qkvb, int* __restrict__ cnt)
{
    int i = blockIdx.x * 256 + threadIdx.x;
    if (i < QKV_W4) {
        int row = i / (QKVN/4);
        int c4  = (i - row * (QKVN/4)) * 4;
        const float* src;
        float scale = 1.f;
        if (c4 < 512)       { src = wq + (size_t)row*512  + c4;         scale = 0.125f; }
        else if (c4 < 1536) { src = wk + (size_t)row*1024 + (c4-512);  }
        else                { src = wv + (size_t)row*1024 + (c4-1536); }
        float4 a = *(const float4*)src;
        __half2 h0 = __floats2half2_rn(a.x*scale, a.y*scale);
        __half2 h1 = __floats2half2_rn(a.z*scale, a.w*scale);
        uint2 u; u.x = *(uint32_t*)&h0; u.y = *(uint32_t*)&h1;
        *(uint2*)(out + (size_t)row * QKVN + c4) = u;
    } else {
        int j = i - QKV_W4;
        if (j < 512)        qkvb[j] = bq[j] * 0.125f;
        else if (j < 1536)  qkvb[j] = bk[j - 512];
        else if (j < QKVN)  qkvb[j] = bv[j - 1536];
        else if (j < QKVN + Ez) cnt[j - QKVN] = 0;
    }
}

// ---------------------------------------------------------------------------
// Mega convert: wo + gw1 (hi/lo split) + ew1 + ew2 in ONE launch.
// ---------------------------------------------------------------------------
#define WO4  (Dz*Dz/4)
#define GW4  (Dz*GHz/4)
#define EW4  ((int)((size_t)Ez*Dz*EDz/4))
#define REST_TOTAL (WO4 + GW4 + 2*EW4)
__global__ __launch_bounds__(256) void cvt_rest(
    const float* __restrict__ wo,  __half* __restrict__ woh,
    const float* __restrict__ gw1, __half* __restrict__ gw1h, __half* __restrict__ gw1l,
    const float* __restrict__ ew1, __half* __restrict__ ew1h,
    const float* __restrict__ ew2, __half* __restrict__ ew2h)
{
    int i = blockIdx.x * 256 + threadIdx.x;
    if (i >= REST_TOTAL) return;
    if (i < WO4) {
        float4 a = ((const float4*)wo)[i];
        __half2 h0 = __floats2half2_rn(a.x, a.y);
        __half2 h1 = __floats2half2_rn(a.z, a.w);
        uint2 u; u.x = *(uint32_t*)&h0; u.y = *(uint32_t*)&h1;
        ((uint2*)woh)[i] = u;
    } else if (i < WO4 + GW4) {
        int k = i - WO4;
        float4 a = ((const float4*)gw1)[k];
        __half hx = __float2half_rn(a.x), hy = __float2half_rn(a.y);
        __half hz = __float2half_rn(a.z), hw = __float2half_rn(a.w);
        __half2 H0; H0.x = hx; H0.y = hy;
        __half2 H1; H1.x = hz; H1.y = hw;
        __half2 L0 = __floats2half2_rn(a.x - __half2float(hx), a.y - __half2float(hy));
        __half2 L1 = __floats2half2_rn(a.z - __half2float(hz), a.w - __half2float(hw));
        uint2 uh; uh.x = *(uint32_t*)&H0; uh.y = *(uint32_t*)&H1;
        uint2 ul; ul.x = *(uint32_t*)&L0; ul.y = *(uint32_t*)&L1;
        ((uint2*)gw1h)[k] = uh;
        ((uint2*)gw1l)[k] = ul;
    } else {
        const float* in; __half* o; int k;
        if (i < WO4 + GW4 + EW4) { in = ew1; o = ew1h; k = i - WO4 - GW4; }
        else                     { in = ew2; o = ew2h; k = i - WO4 - GW4 - EW4; }
        float4 a = ((const float4*)in)[k];
        __half2 h0 = __floats2half2_rn(a.x, a.y);
        __half2 h1 = __floats2half2_rn(a.z, a.w);
        uint2 u; u.x = *(uint32_t*)&h0; u.y = *(uint32_t*)&h1;
        ((uint2*)o)[k] = u;
    }
}

// ---------------------------------------------------------------------------
// LayerNorm: one block per token row of 1024.
// ---------------------------------------------------------------------------
template<bool SPLIT>
__global__ __launch_bounds__(256) void ln_kernel(
    const float* __restrict__ X, const float* __restrict__ g,
    const float* __restrict__ b, __half* __restrict__ O16, __half* __restrict__ OLO)
{
    int t = blockIdx.x;
    int tid = threadIdx.x;
    const float4* x4 = (const float4*)(X + (size_t)t * Dz);
    float4 xv = x4[tid];
    float s  = xv.x + xv.y + xv.z + xv.w;
    float ss = xv.x*xv.x + xv.y*xv.y + xv.z*xv.z + xv.w*xv.w;
    #pragma unroll
    for (int off = 16; off; off >>= 1) {
        s  += __shfl_xor_sync(0xffffffffu, s,  off);
        ss += __shfl_xor_sync(0xffffffffu, ss, off);
    }
    __shared__ float sh_s[8], sh_ss[8];
    if ((tid & 31) == 0) { sh_s[tid >> 5] = s; sh_ss[tid >> 5] = ss; }
    __syncthreads();
    if (tid < 32) {
        float a = (tid < 8) ? sh_s[tid]  : 0.f;
        float c = (tid < 8) ? sh_ss[tid] : 0.f;
        #pragma unroll
        for (int off = 4; off; off >>= 1) {
            a += __shfl_xor_sync(0xffffffffu, a, off);
            c += __shfl_xor_sync(0xffffffffu, c, off);
        }
        if (tid == 0) { sh_s[0] = a; sh_ss[0] = c; }
    }
    __syncthreads();
    float mu  = sh_s[0]  * (1.f / Dz);
    float var = sh_ss[0] * (1.f / Dz) - mu * mu;
    float inv = rsqrtf(var + 1e-5f);
    float4 gv = ((const float4*)g)[tid];
    float4 bv = ((const float4*)b)[tid];
    float4 o;
    o.x = (xv.x - mu) * inv * gv.x + bv.x;
    o.y = (xv.y - mu) * inv * gv.y + bv.y;
    o.z = (xv.z - mu) * inv * gv.z + bv.z;
    o.w = (xv.w - mu) * inv * gv.w + bv.w;
    __half hx = __float2half_rn(o.x), hy = __float2half_rn(o.y);
    __half hz = __float2half_rn(o.z), hw = __float2half_rn(o.w);
    __half2 p0; p0.x = hx; p0.y = hy;
    __half2 p1; p1.x = hz; p1.y = hw;
    uint2 u; u.x = *(uint32_t*)&p0; u.y = *(uint32_t*)&p1;
    ((uint2*)(O16 + (size_t)t * Dz))[tid] = u;
    if (SPLIT) {
        __half2 l0 = __floats2half2_rn(o.x - __half2float(hx), o.y - __half2float(hy));
        __half2 l1 = __floats2half2_rn(o.z - __half2float(hz), o.w - __half2float(hw));
        uint2 ul; ul.x = *(uint32_t*)&l0; ul.y = *(uint32_t*)&l1;
        ((uint2*)(OLO + (size_t)t * Dz))[tid] = ul;
    }
}

// ---------------------------------------------------------------------------
// fp16 tensor-core GEMM with cp.async.bulk staging (LSU-issue relief).
// C[M,N] = act(A @ B + bias)(+resid).
// GMODE: 0 dense; 2 A gathered via elist (>>ashift), C dense at e*Tz+m;
//        3 A dense at e*Tz+m, C scattered via elist.
// BM=128, BN=128, BK=64 halves, 256 threads, warp 64x32.
// Staging: per k-tile, threads 0-127 bulk-copy one A row (128 B) each,
// threads 128-191 one B row (256 B) each; mbarrier count=192, tx-bytes.
// 3-stage ring; __syncthreads before re-staging a stage.
// smem: 32 B mbarriers | A[3][128 rows x 144 B] | B[3][64 rows x 272 B].
// ---------------------------------------------------------------------------
#define GEMMH_SMEM (32 + 3*128*144 + 3*64*272)
template<int ACT, int GMODE, bool RESID, bool OUTH>
__global__ void __launch_bounds__(256,2) gemm_hc(
    const __half* __restrict__ A, const __half* __restrict__ B,
    const float* __restrict__ bias, void* __restrict__ Cv,
    int M, int N, int K,
    const float* __restrict__ resid,
    const int* __restrict__ elist, const int* __restrict__ cnt, int ashift)
{
    extern __shared__ __align__(16) char smraw[];
    uint32_t sb = s2u(smraw);
    uint32_t mb = sb;                       // 3 mbarriers (8 B each)
    uint32_t Au = sb + 32;
    uint32_t Bu = Au + 3*128*144;
    const uint32_t abuf = 128*144, bbuf = 64*272;

    int e = blockIdx.z;
    const __half* Bp = B + (size_t)e * K * N;
    const float*  bp = bias + (size_t)e * N;
    int mcount = (GMODE != 0) ? cnt[e] : M;
    int m0 = blockIdx.y * 128;
    if (m0 >= mcount) return;
    int n0 = blockIdx.x * 128;
    const int* lst = (GMODE != 0) ? (elist + e * Tz) : (const int*)nullptr;

    int tid = threadIdx.x;
    int lane = tid & 31, wid = tid >> 5;
    int warpM = wid >> 2, warpN = wid & 3;

    if (tid == 0) {
        mbar_init(mb, 192); mbar_init(mb + 8, 192); mbar_init(mb + 16, 192);
    }
    __syncthreads();

    // staging roles
    const __half* arow = nullptr; bool av = false; uint32_t ad = 0;
    const __half* brow = nullptr; uint32_t bd = 0;
    if (tid < 128) {
        int m = m0 + tid;
        av = (m < mcount);
        size_t rowg;
        if (GMODE == 2)      rowg = av ? (size_t)(lst[m] >> ashift) : 0;
        else if (GMODE == 3) rowg = av ? (size_t)(e * Tz + m) : 0;
        else                 rowg = av ? (size_t)m : 0;
        arow = A + rowg * (size_t)K;
        ad = Au + (uint32_t)tid * 144;
    } else if (tid < 192) {
        int r = tid - 128;
        brow = Bp + (size_t)r * N + n0;
        bd = Bu + (uint32_t)r * 272;
    }

    auto stage = [&](int kt2, int s){
        uint32_t m_ = mb + (uint32_t)s * 8;
        if (tid < 128) {
            if (av) { mbar_expect(m_, 128); cpbulk(ad + (uint32_t)s*abuf, arow + kt2*64, 128, m_); }
            else    { mbar_arrive(m_); }
        } else if (tid < 192) {
            mbar_expect(m_, 256);
            cpbulk(bd + (uint32_t)s*bbuf, brow + (size_t)(kt2*64)*N, 256, m_);
        }
    };

    float acc[4][4][4];
    #pragma unroll
    for (int i=0;i<4;i++)
        #pragma unroll
        for (int j=0;j<4;j++)
            #pragma unroll
            for (int l=0;l<4;l++) acc[i][j][l] = 0.f;

    int KT = K / 64;
    stage(0, 0); stage(1, 1); stage(2, 2);

    uint32_t lr = lane & 15, lc = (lane >> 4) * 8;
    for (int kt = 0; kt < KT; kt++) {
        int s = kt % 3;
        mbar_wait(mb + (uint32_t)s*8, (uint32_t)((kt/3) & 1));

        uint32_t abase = Au + (uint32_t)s*abuf + ((warpM*64 + lr)*72 + lc)*2;
        uint32_t bbase = Bu + (uint32_t)s*bbuf + (lr*136 + warpN*32 + lc)*2;
        #pragma unroll
        for (int ks = 0; ks < 4; ks++) {
            uint32_t ah[4][4];
            #pragma unroll
            for (int mt = 0; mt < 4; mt++)
                ldm4(ah[mt], abase + (mt*16*72 + ks*16)*2);
            uint32_t bt[2][4];
            #pragma unroll
            for (int pr = 0; pr < 2; pr++)
                ldm4t(bt[pr], bbase + (ks*16*136 + pr*16)*2);
            #pragma unroll
            for (int mt = 0; mt < 4; mt++) {
                mma16(acc[mt][0], ah[mt], bt[0][0], bt[0][1]);
                mma16(acc[mt][1], ah[mt], bt[0][2], bt[0][3]);
                mma16(acc[mt][2], ah[mt], bt[1][0], bt[1][1]);
                mma16(acc[mt][3], ah[mt], bt[1][2], bt[1][3]);
            }
        }
        __syncthreads();
        if (kt + 3 < KT) stage(kt + 3, s);
    }

    float2 bv[4];
    #pragma unroll
    for (int nt = 0; nt < 4; nt++)
        bv[nt] = *(const float2*)(bp + n0 + warpN*32 + (lane&3)*2 + nt*8);

    float*  Cf = (float*)Cv;
    __half* Ch = (__half*)Cv;
    #pragma unroll
    for (int mt = 0; mt < 4; mt++) {
        #pragma unroll
        for (int hf = 0; hf < 2; hf++) {
            int r = m0 + warpM*64 + mt*16 + (lane>>2) + hf*8;
            if (r >= mcount) continue;
            size_t crow;
            if (GMODE == 2)      crow = (size_t)(e * Tz + r);
            else if (GMODE == 3) crow = (size_t)lst[r];
            else                 crow = (size_t)r;
            int coff = n0 + warpN*32 + (lane&3)*2;
            const float* Rr = RESID ? (resid + crow*(size_t)N + coff) : (const float*)nullptr;
            #pragma unroll
            for (int nt = 0; nt < 4; nt++) {
                float v0 = acc[mt][nt][hf*2+0] + bv[nt].x;
                float v1 = acc[mt][nt][hf*2+1] + bv[nt].y;
                if (ACT == 1) { v0 = fmaxf(v0, 0.f); v1 = fmaxf(v1, 0.f); }
                if (ACT == 2) {
                    v0 = 0.5f*v0*(1.f + erff(v0*0.70710678118654752f));
                    v1 = 0.5f*v1*(1.f + erff(v1*0.70710678118654752f));
                }
                if (RESID) { v0 += Rr[nt*8]; v1 += Rr[nt*8+1]; }
                if (OUTH) {
                    __half2 h = __floats2half2_rn(v0, v1);
                    *(__half2*)(Ch + crow*(size_t)N + coff + nt*8) = h;
                } else {
                    float2 o; o.x = v0; o.y = v1;
                    *(float2*)(Cf + crow*(size_t)N + coff + nt*8) = o;
                }
            }
        }
    }
}

// ---------------------------------------------------------------------------
// Split-fp16 gate GEMM (near-fp32), cp.async staging (control / unchanged).
// ---------------------------------------------------------------------------
#define GATE_SMEM (2*2*128*40*2 + 2*2*32*136*2)
__global__ void __launch_bounds__(256,2) gemm_gate16(
    const __half* __restrict__ Ah, const __half* __restrict__ Al,
    const __half* __restrict__ Bh, const __half* __restrict__ Bl,
    const float* __restrict__ bias, float* __restrict__ C,
    int M, int N, int K)
{
    extern __shared__ __half smh[];
    __half* Ahs = smh;                        // [2][128][40]
    __half* Als = Ahs + 2*128*40;             // [2][128][40]
    __half* Bhs = Als + 2*128*40;             // [2][32][136]
    __half* Bls = Bhs + 2*32*136;             // [2][32][136]

    int m0 = blockIdx.y * 128;
    int n0 = blockIdx.x * 128;
    int tid = threadIdx.x;
    int lane = tid & 31, wid = tid >> 5;
    int warpM = wid >> 2, warpN = wid & 3;

    int arow = tid >> 1, acol = (tid & 1) * 16;
    const __half* ahp = Ah + (size_t)(m0 + arow) * K + acol;
    const __half* alp = Al + (size_t)(m0 + arow) * K + acol;
    uint32_t ahd = s2u(&Ahs[arow * 40 + acol]);
    uint32_t ald = s2u(&Als[arow * 40 + acol]);
    int brow = tid >> 3, bcol = (tid & 7) * 16;
    const __half* bhp = Bh + (size_t)brow * N + n0 + bcol;
    const __half* blp = Bl + (size_t)brow * N + n0 + bcol;
    uint32_t bhd = s2u(&Bhs[brow * 136 + bcol]);
    uint32_t bld = s2u(&Bls[brow * 136 + bcol]);

    const uint32_t abuf = 128*40*2, bbuf = 32*136*2;

    auto stage = [&](int kt, int buf){
        int k0 = kt * 32;
        cpa16(ahd + buf*abuf,      ahp + k0, true);
        cpa16(ahd + buf*abuf + 16, ahp + k0 + 8, true);
        cpa16(ald + buf*abuf,      alp + k0, true);
        cpa16(ald + buf*abuf + 16, alp + k0 + 8, true);
        cpa16(bhd + buf*bbuf,      bhp + (size_t)k0*N, true);
        cpa16(bhd + buf*bbuf + 16, bhp + (size_t)k0*N + 8, true);
        cpa16(bld + buf*bbuf,      blp + (size_t)k0*N, true);
        cpa16(bld + buf*bbuf + 16, blp + (size_t)k0*N + 8, true);
    };

    uint32_t ahs_u = s2u(Ahs), als_u = s2u(Als);
    uint32_t bhs_u = s2u(Bhs), bls_u = s2u(Bls);

    float acc[4][4][4];
    #pragma unroll
    for (int i=0;i<4;i++)
        #pragma unroll
        for (int j=0;j<4;j++)
            #pragma unroll
            for (int l=0;l<4;l++) acc[i][j][l] = 0.f;

    int KT = K / 32;
    stage(0, 0); cp_commit();

    uint32_t lr = lane & 15, lc = (lane >> 4) * 8;
    for (int kt = 0; kt < KT; kt++) {
        int buf = kt & 1;
        cp_wait0();
        __syncthreads();
        if (kt + 1 < KT) { stage(kt+1, buf ^ 1); }
        cp_commit();

        uint32_t aoff = ((uint32_t)buf*(128*40) + (warpM*64 + lr)*40 + lc)*2;
        uint32_t boff = ((uint32_t)buf*(32*136) + lr*136 + warpN*32 + lc)*2;
        #pragma unroll
        for (int ks = 0; ks < 2; ks++) {
            uint32_t ah[4][4], al[4][4];
            #pragma unroll
            for (int mt = 0; mt < 4; mt++) {
                ldm4(ah[mt], ahs_u + aoff + (mt*16*40 + ks*16)*2);
                ldm4(al[mt], als_u + aoff + (mt*16*40 + ks*16)*2);
            }
            uint32_t bth[2][4], btl[2][4];
            #pragma unroll
            for (int pr = 0; pr < 2; pr++) {
                ldm4t(bth[pr], bhs_u + boff + (ks*16*136 + pr*16)*2);
                ldm4t(btl[pr], bls_u + boff + (ks*16*136 + pr*16)*2);
            }
            #pragma unroll
            for (int mt = 0; mt < 4; mt++) {
                mma16(acc[mt][0], ah[mt], bth[0][0], bth[0][1]);
                mma16(acc[mt][1], ah[mt], bth[0][2], bth[0][3]);
                mma16(acc[mt][2], ah[mt], bth[1][0], bth[1][1]);
                mma16(acc[mt][3], ah[mt], bth[1][2], bth[1][3]);
                mma16(acc[mt][0], al[mt], bth[0][0], bth[0][1]);
                mma16(acc[mt][1], al[mt], bth[0][2], bth[0][3]);
                mma16(acc[mt][2], al[mt], bth[1][0], bth[1][1]);
                mma16(acc[mt][3], al[mt], bth[1][2], bth[1][3]);
                mma16(acc[mt][0], ah[mt], btl[0][0], btl[0][1]);
                mma16(acc[mt][1], ah[mt], btl[0][2], btl[0][3]);
                mma16(acc[mt][2], ah[mt], btl[1][0], btl[1][1]);
                mma16(acc[mt][3], ah[mt], btl[1][2], btl[1][3]);
            }
        }
    }

    float2 bv[4];
    #pragma unroll
    for (int nt = 0; nt < 4; nt++)
        bv[nt] = *(const float2*)(bias + n0 + warpN*32 + (lane&3)*2 + nt*8);

    #pragma unroll
    for (int mt = 0; mt < 4; mt++)
        #pragma unroll
        for (int hf = 0; hf < 2; hf++) {
            int r = m0 + warpM*64 + mt*16 + (lane>>2) + hf*8;
            float* Cr = C + (size_t)r*N + n0 + warpN*32 + (lane&3)*2;
            #pragma unroll
            for (int nt = 0; nt < 4; nt++) {
                float v0 = fmaxf(acc[mt][nt][hf*2+0] + bv[nt].x, 0.f);
                float v1 = fmaxf(acc[mt][nt][hf*2+1] + bv[nt].y, 0.f);
                float2 o; o.x = v0; o.y = v1;
                *(float2*)(Cr + nt*8) = o;
            }
        }
}

// ---------------------------------------------------------------------------
// Fused flash attention; K/V staged via cp.async.bulk + mbarrier (2-stage),
// Q via cp.async (one-shot). fp16 mma.sync, online softmax.
// smem: 32 B mbarriers | Ps[128 rows x 272 B] (alias Q rows 144 B) |
//       K[2][128x144 B] | V[2][128x144 B]
// ---------------------------------------------------------------------------
#define FA_SMEM (32 + 128*272 + 4*128*144)
__global__ void __launch_bounds__(256,2) fa_h(
    const __half* __restrict__ QKV, __half* __restrict__ O)
{
    extern __shared__ __align__(16) char smraw[];
    uint32_t sb = s2u(smraw);
    uint32_t mbr = sb;                 // 2 mbarriers
    uint32_t Pu  = sb + 32;            // [128][136] halves
    uint32_t Ku  = Pu + 128*272;       // [2][128][72] halves
    uint32_t Vu  = Ku + 2*128*144;
    const uint32_t kvbuf = 128*144;

    int bh = blockIdx.y, b = bh >> 4, h = bh & 15, g = h >> 1;
    int q0 = blockIdx.x * 128;
    int tid = threadIdx.x, lane = tid & 31, w = tid >> 5;

    if (tid == 0) { mbar_init(mbr, 256); mbar_init(mbr + 8, 256); }
    __syncthreads();

    // Q staging (cp.async, one group)
    const __half* Qb = QKV + (size_t)(b*Sz + q0) * QKVN + g*64;
    {
        int row = tid >> 1;
        #pragma unroll
        for (int j = 0; j < 4; j++) {
            int c = (tid & 1) + 2*j;
            cpa16(Pu + (uint32_t)row*144 + (uint32_t)c*16, Qb + (size_t)row*QKVN + c*8, true);
        }
    }
    cp_commit();

    // K/V bulk staging: thread<128 -> K row tid, else V row tid-128 (128 B each)
    const __half* Kb = QKV + (size_t)(b*Sz)*QKVN + 512 + h*64;
    const __half* Vb = QKV + (size_t)(b*Sz)*QKVN + 1536 + h*64;
    const __half* kvrow;
    uint32_t kvd;
    if (tid < 128) { kvrow = Kb + (size_t)tid*QKVN;        kvd = Ku + (uint32_t)tid*144; }
    else           { kvrow = Vb + (size_t)(tid-128)*QKVN;  kvd = Vu + (uint32_t)(tid-128)*144; }

    auto stageKV = [&](int kt, int s){
        uint32_t m_ = mbr + (uint32_t)s*8;
        mbar_expect(m_, 128);
        cpbulk(kvd + (uint32_t)s*kvbuf, kvrow + (size_t)(kt*128)*QKVN, 128, m_);
    };
    stageKV(0, 0);
    stageKV(1, 1);

    cp_wait0();
    __syncthreads();
    uint32_t lr = lane & 15, lc = (lane >> 4) * 8;
    uint32_t qbase = Pu + ((w*16 + lr)*72 + lc)*2;
    uint32_t qf[4][4];
    #pragma unroll
    for (int ks = 0; ks < 4; ks++) ldm4(qf[ks], qbase + ks*32);
    __syncthreads();   // Ps region reusable for P

    float m0 = -INFINITY, m1 = -INFINITY, l0 = 0.f, l1 = 0.f;
    float oacc[8][4];
    #pragma unroll
    for (int i=0;i<8;i++)
        #pragma unroll
        for (int j=0;j<4;j++) oacc[i][j] = 0.f;

    uint32_t pabase = Pu + ((w*16 + lr)*136 + lc)*2;
    uint32_t prow_u = Pu + ((w*16 + (lane>>2))*136 + (lane&3)*2)*2;
    __half* prow = (__half*)(smraw + (prow_u - sb));

    for (int kt = 0; kt < 8; kt++) {
        int s = kt & 1;
        mbar_wait(mbr + (uint32_t)s*8, (uint32_t)((kt >> 1) & 1));

        // ---- S = Q @ K^T ----
        float sacc[16][4];
        #pragma unroll
        for (int i=0;i<16;i++)
            #pragma unroll
            for (int j=0;j<4;j++) sacc[i][j] = 0.f;
        uint32_t kbase = Ku + (uint32_t)s*kvbuf + (lr*72 + lc)*2;
        #pragma unroll
        for (int ks = 0; ks < 4; ks++) {
            #pragma unroll
            for (int np = 0; np < 8; np++) {
                uint32_t r[4];
                ldm4(r, kbase + (np*16*72 + ks*16)*2);
                mma16(sacc[2*np  ], qf[ks], r[0], r[2]);
                mma16(sacc[2*np+1], qf[ks], r[1], r[3]);
            }
        }

        // ---- online softmax ----
        float t0 = -INFINITY, t1 = -INFINITY;
        #pragma unroll
        for (int nt = 0; nt < 16; nt++) {
            t0 = fmaxf(t0, fmaxf(sacc[nt][0], sacc[nt][1]));
            t1 = fmaxf(t1, fmaxf(sacc[nt][2], sacc[nt][3]));
        }
        t0 = fmaxf(t0, __shfl_xor_sync(0xffffffffu, t0, 1));
        t0 = fmaxf(t0, __shfl_xor_sync(0xffffffffu, t0, 2));
        t1 = fmaxf(t1, __shfl_xor_sync(0xffffffffu, t1, 1));
        t1 = fmaxf(t1, __shfl_xor_sync(0xffffffffu, t1, 2));
        float mn0 = fmaxf(m0, t0), mn1 = fmaxf(m1, t1);
        float sc0 = __expf(m0 - mn0), sc1 = __expf(m1 - mn1);
        float s0 = 0.f, s1 = 0.f;
        #pragma unroll
        for (int nt = 0; nt < 16; nt++) {
            sacc[nt][0] = __expf(sacc[nt][0] - mn0);
            sacc[nt][1] = __expf(sacc[nt][1] - mn0);
            sacc[nt][2] = __expf(sacc[nt][2] - mn1);
            sacc[nt][3] = __expf(sacc[nt][3] - mn1);
            s0 += sacc[nt][0] + sacc[nt][1];
            s1 += sacc[nt][2] + sacc[nt][3];
        }
        s0 += __shfl_xor_sync(0xffffffffu, s0, 1);
        s0 += __shfl_xor_sync(0xffffffffu, s0, 2);
        s1 += __shfl_xor_sync(0xffffffffu, s1, 1);
        s1 += __shfl_xor_sync(0xffffffffu, s1, 2);
        l0 = l0*sc0 + s0; l1 = l1*sc1 + s1;
        m0 = mn0; m1 = mn1;
        #pragma unroll
        for (int nt = 0; nt < 8; nt++) {
            oacc[nt][0] *= sc0; oacc[nt][1] *= sc0;
            oacc[nt][2] *= sc1; oacc[nt][3] *= sc1;
        }

        // ---- P -> smem fp16 (own rows only) ----
        #pragma unroll
        for (int nt = 0; nt < 16; nt++) {
            *(__half2*)(prow + nt*8)          = __floats2half2_rn(sacc[nt][0], sacc[nt][1]);
            *(__half2*)(prow + 8*136 + nt*8)  = __floats2half2_rn(sacc[nt][2], sacc[nt][3]);
        }
        __syncwarp();

        // ---- O += P @ V ----
        uint32_t vbase = Vu + (uint32_t)s*kvbuf + (lr*72 + lc)*2;
        #pragma unroll
        for (int k2 = 0; k2 < 8; k2++) {
            uint32_t pf[4];
            ldm4(pf, pabase + k2*32);
            #pragma unroll
            for (int hp = 0; hp < 4; hp++) {
                uint32_t vt[4];
                ldm4t(vt, vbase + (k2*16*72 + hp*16)*2);
                mma16(oacc[2*hp  ], pf, vt[0], vt[1]);
                mma16(oacc[2*hp+1], pf, vt[2], vt[3]);
            }
        }

        __syncthreads();
        if (kt + 2 < 8) stageKV(kt + 2, s);
    }

    float i0 = 1.f / l0, i1 = 1.f / l1;
    int r0 = q0 + w*16 + (lane >> 2);
    __half* Op = O + (size_t)(b*Sz + r0)*1024 + h*64 + (lane&3)*2;
    #pragma unroll
    for (int nt = 0; nt < 8; nt++) {
        *(__half2*)(Op + nt*8)          = __floats2half2_rn(oacc[nt][0]*i0, oacc[nt][1]*i0);
        *(__half2*)(Op + 8*1024 + nt*8) = __floats2half2_rn(oacc[nt][2]*i1, oacc[nt][3]*i1);
    }
}

// ---------------------------------------------------------------------------
// Gate head + softmax + top-2 + renorm + routing. One warp per token.
// ---------------------------------------------------------------------------
__global__ __launch_bounds__(256) void gate_route_kernel(
    const float* __restrict__ GH, const float* __restrict__ gw2,
    const float* __restrict__ gb2,
    float* __restrict__ wout, int* __restrict__ cnt, int* __restrict__ elist)
{
    int warp = threadIdx.x >> 5;
    int lane = threadIdx.x & 31;
    int t = blockIdx.x * 8 + warp;
    if (t >= Tz) return;

    float logit[Ez];
    #pragma unroll
    for (int o = 0; o < Ez; o++) {
        float s = 0.f;
        for (int i = lane; i < GHz; i += 32)
            s += GH[(size_t)t * GHz + i] * gw2[(size_t)i * Ez + o];
        #pragma unroll
        for (int off = 16; off; off >>= 1)
            s += __shfl_xor_sync(0xffffffffu, s, off);
        logit[o] = s + gb2[o];
    }
    if (lane == 0) {
        float m = logit[0];
        #pragma unroll
        for (int o = 1; o < Ez; o++) m = fmaxf(m, logit[o]);
        float w[Ez], sum = 0.f;
        #pragma unroll
        for (int o = 0; o < Ez; o++) { w[o] = expf(logit[o] - m); sum += w[o]; }
        float invs = 1.f / sum;
        #pragma unroll
        for (int o = 0; o < Ez; o++) w[o] *= invs;
        int i0 = 0; float v0 = w[0];
        #pragma unroll
        for (int o = 1; o < Ez; o++) if (w[o] > v0) { v0 = w[o]; i0 = o; }
        int i1 = -1; float v1 = -1.f;
        #pragma unroll
        for (int o = 0; o < Ez; o++)
            if (o != i0 && w[o] > v1) { v1 = w[o]; i1 = o; }
        float e1 = expf(v1 - v0);
        float den = 1.f + e1;
        wout[2*t + 0] = 1.f / den;
        wout[2*t + 1] = e1 / den;
        int p0 = atomicAdd(&cnt[i0], 1);
        elist[i0 * Tz + p0] = 2*t + 0;
        int p1 = atomicAdd(&cnt[i1], 1);
        elist[i1 * Tz + p1] = 2*t + 1;
    }
}

// ---------------------------------------------------------------------------
// Final combine: out = x1 + w0*eo[2t] + w1*eo[2t+1]  (eo fp16)
// ---------------------------------------------------------------------------
__global__ __launch_bounds__(256) void combine_kernel(
    const float* __restrict__ x1, const __half* __restrict__ eo,
    const float* __restrict__ w, float* __restrict__ out)
{
    int idx = blockIdx.x * 256 + threadIdx.x;
    int t = idx >> 8;
    int c = idx & 255;
    float w0 = w[2*t], w1 = w[2*t + 1];
    float4 a  = ((const float4*)x1)[idx];
    uint2 u0 = ((const uint2*)(eo + (size_t)(2*t)     * Dz))[c];
    uint2 u1 = ((const uint2*)(eo + (size_t)(2*t + 1) * Dz))[c];
    float2 e0a = __half22float2(*(__half2*)&u0.x);
    float2 e0b = __half22float2(*(__half2*)&u0.y);
    float2 e1a = __half22float2(*(__half2*)&u1.x);
    float2 e1b = __half22float2(*(__half2*)&u1.y);
    float4 r;
    r.x = a.x + w0 * e0a.x + w1 * e1a.x;
    r.y = a.y + w0 * e0a.y + w1 * e1a.y;
    r.z = a.z + w0 * e0b.x + w1 * e1b.x;
    r.w = a.w + w0 * e0b.y + w1 * e1b.y;
    ((float4*)out)[idx] = r;
}

// ---------------------------------------------------------------------------
// Host launch (single stream — graph-capture safe)
// ---------------------------------------------------------------------------
extern "C" void kernel_launch(void* const* d_in, const int* in_sizes, int n_in,
                              void* d_out, int out_size)
{
    const float* x    = (const float*)d_in[0];
    const float* wq   = (const float*)d_in[1];
    const float* bq   = (const float*)d_in[2];
    const float* wk   = (const float*)d_in[3];
    const float* bk   = (const float*)d_in[4];
    const float* wv   = (const float*)d_in[5];
    const float* bv   = (const float*)d_in[6];
    const float* wo   = (const float*)d_in[7];
    const float* bo   = (const float*)d_in[8];
    const float* ln1g = (const float*)d_in[9];
    const float* ln1b = (const float*)d_in[10];
    const float* ln2g = (const float*)d_in[11];
    const float* ln2b = (const float*)d_in[12];
    const float* gw1  = (const float*)d_in[13];
    const float* gb1  = (const float*)d_in[14];
    const float* gw2  = (const float*)d_in[15];
    const float* gb2  = (const float*)d_in[16];
    const float* ew1  = (const float*)d_in[17];
    const float* eb1  = (const float*)d_in[18];
    const float* ew2  = (const float*)d_in[19];
    const float* eb2  = (const float*)d_in[20];
    float* out = (float*)d_out;

    __half *h1h, *qkvh, *aoh, *h2h, *h2l, *hidh, *eo;
    __half *wqkvh, *woh, *ew1h, *ew2h, *gw1h, *gw1l;
    float *x1, *gh, *w, *qkvb;
    int *cnt, *elist;
    cudaGetSymbolAddress((void**)&h1h,  g_h1h);
    cudaGetSymbolAddress((void**)&qkvh, g_qkvh);
    cudaGetSymbolAddress((void**)&aoh,  g_aoh);
    cudaGetSymbolAddress((void**)&x1,   g_x1);
    cudaGetSymbolAddress((void**)&h2h,  g_h2h);
    cudaGetSymbolAddress((void**)&h2l,  g_h2l);
    cudaGetSymbolAddress((void**)&gh,   g_gh);
    cudaGetSymbolAddress((void**)&w,    g_w);
    cudaGetSymbolAddress((void**)&hidh, g_hidh);
    cudaGetSymbolAddress((void**)&eo,   g_eo);
    cudaGetSymbolAddress((void**)&cnt,  g_cnt);
    cudaGetSymbolAddress((void**)&elist,g_elist);
    cudaGetSymbolAddress((void**)&wqkvh,g_wqkvh);
    cudaGetSymbolAddress((void**)&woh,  g_woh);
    cudaGetSymbolAddress((void**)&ew1h, g_ew1h);
    cudaGetSymbolAddress((void**)&ew2h, g_ew2h);
    cudaGetSymbolAddress((void**)&gw1h, g_gw1h);
    cudaGetSymbolAddress((void**)&gw1l, g_gw1l);
    cudaGetSymbolAddress((void**)&qkvb, g_qkvb);

    cudaFuncSetAttribute(gemm_hc<0,0,false,true>, cudaFuncAttributeMaxDynamicSharedMemorySize, GEMMH_SMEM);
    cudaFuncSetAttribute(gemm_hc<0,0,true,false>, cudaFuncAttributeMaxDynamicSharedMemorySize, GEMMH_SMEM);
    cudaFuncSetAttribute(gemm_hc<2,2,false,true>, cudaFuncAttributeMaxDynamicSharedMemorySize, GEMMH_SMEM);
    cudaFuncSetAttribute(gemm_hc<0,3,false,true>, cudaFuncAttributeMaxDynamicSharedMemorySize, GEMMH_SMEM);
    cudaFuncSetAttribute(gemm_gate16, cudaFuncAttributeMaxDynamicSharedMemorySize, GATE_SMEM);
    cudaFuncSetAttribute(fa_h, cudaFuncAttributeMaxDynamicSharedMemorySize, FA_SMEM);

    // launch 0: fused qkv weight convert + bias pack + count zero
    cvt_qkv<<<(QKV_W4 + QKVN + Ez + 255)/256, 256>>>(
        wq, wk, wv, bq, bk, bv, wqkvh, qkvb, cnt);
    // launch 1: all remaining weight converts in one HBM-bound pass
    cvt_rest<<<(REST_TOTAL + 255)/256, 256>>>(
        wo, woh, gw1, gw1h, gw1l, ew1, ew1h, ew2, ew2h);

    // LN1
    ln_kernel<false><<<Tz, 256>>>(x, ln1g, ln1b, h1h, nullptr);

    // Fused QKV projection
    gemm_hc<0,0,false,true><<<dim3(QKVN/128, 32, 1), 256, GEMMH_SMEM>>>(
        h1h, wqkvh, qkvb, qkvh, Tz, QKVN, Dz, nullptr, nullptr, nullptr, 0);

    fa_h<<<dim3(Sz/128, Bz*Hh), 256, FA_SMEM>>>(qkvh, aoh);

    // Output projection + residual -> x1 fp32
    gemm_hc<0,0,true,false><<<dim3(8, 32, 1), 256, GEMMH_SMEM>>>(
        aoh, woh, bo, x1, Tz, Dz, Dz, x, nullptr, nullptr, 0);

    ln_kernel<true><<<Tz, 256>>>(x1, ln2g, ln2b, h2h, h2l);

    gemm_gate16<<<dim3(GHz/128, Tz/128, 1), 256, GATE_SMEM>>>(
        h2h, h2l, gw1h, gw1l, gb1, gh, Tz, GHz, Dz);

    gate_route_kernel<<<Tz/8, 256>>>(gh, gw2, gb2, w, cnt, elist);

    // Expert FFN: GEMM1 A-gathered / C-dense (hid rows e*Tz+m),
    //             GEMM2 A-dense / C-scattered (eo rows = assignment id)
    gemm_hc<2,2,false,true><<<dim3(EDz/128, Tz/128, Ez), 256, GEMMH_SMEM>>>(
        h2h, ew1h, eb1, hidh, Tz, EDz, Dz, nullptr, elist, cnt, 1);
    gemm_hc<0,3,false,true><<<dim3(Dz/128, Tz/128, Ez), 256, GEMMH_SMEM>>>(
        hidh, ew2h, eb2, eo, Tz, Dz, EDz, nullptr, elist, cnt, 0);

    combine_kernel<<<(Tz*Dz/4)/256, 256>>>(x1, eo, w, out);
}

// round 15
// speedup vs baseline: 1.0192x; 1.0031x over previous
#include <cuda_runtime.h>
#include <cuda_fp16.h>
#include <math.h>
#include <stdint.h>

// ---------------------------------------------------------------------------
// Problem constants
// ---------------------------------------------------------------------------
#define Bz   4
#define Sz   1024
#define Dz   1024
#define Hh   16
#define Gg   8
#define HDz  64
#define Ez   8
#define EDz  2048
#define GHz  512
#define Tz   (Bz*Sz)          // 4096 tokens
#define QKVN 2560             // packed q(512) | k(1024) | v(1024)

// ---------------------------------------------------------------------------
// Scratch (static device memory)
// ---------------------------------------------------------------------------
__device__ __half g_h1h [Tz*Dz];
__device__ __half g_qkvh[(size_t)Tz*QKVN];
__device__ __half g_aoh [Tz*Dz];
__device__ float  g_x1  [Tz*Dz];
__device__ __half g_h2h [Tz*Dz];       // LN2 out, fp16 hi
__device__ __half g_h2l [Tz*Dz];       // LN2 out, fp16 lo (residual)
__device__ float  g_gh  [Tz*GHz];
__device__ float  g_w   [Tz*2];
__device__ int    g_cnt [Ez];
__device__ int    g_elist[Ez*Tz];
__device__ __half g_hidh[(size_t)Ez*Tz*EDz];   // per-expert dense rows (e*Tz + m)
__device__ __half g_eo  [(size_t)Tz*2*Dz];
// fp16 weights ([K][N] row-major; qkv packed) + packed qkv bias
__device__ __half g_wqkvh[(size_t)Dz*QKVN];
__device__ __half g_woh  [(size_t)Dz*Dz];
__device__ __half g_ew1h [(size_t)Ez*Dz*EDz];
__device__ __half g_ew2h [(size_t)Ez*EDz*Dz];
__device__ __half g_gw1h [(size_t)Dz*GHz];   // gate w1 hi
__device__ __half g_gw1l [(size_t)Dz*GHz];   // gate w1 lo
__device__ float  g_qkvb [QKVN];

// ---------------------------------------------------------------------------
// Helpers
// ---------------------------------------------------------------------------
__device__ __forceinline__ uint32_t s2u(const void* p){
    return (uint32_t)__cvta_generic_to_shared(p);
}
__device__ __forceinline__ void cpa16(uint32_t d, const void* s, bool v){
    asm volatile("cp.async.cg.shared.global [%0], [%1], 16, %2;\n"
                 :: "r"(d), "l"(s), "r"(v ? 16 : 0));
}
__device__ __forceinline__ void cp_commit(){ asm volatile("cp.async.commit_group;\n"); }
__device__ __forceinline__ void cp_wait0(){ asm volatile("cp.async.wait_group 0;\n"); }
// Bulk async copy global->shared, completion via mbarrier tx-bytes
__device__ __forceinline__ void cpbulk(uint32_t d, const void* s, uint32_t bytes, uint32_t mbar){
    asm volatile("cp.async.bulk.shared::cluster.global.mbarrier::complete_tx::bytes "
                 "[%0], [%1], %2, [%3];"
                 :: "r"(d), "l"(s), "r"(bytes), "r"(mbar) : "memory");
}
__device__ __forceinline__ void mbar_init(uint32_t mbar, uint32_t cnt){
    asm volatile("mbarrier.init.shared.b64 [%0], %1;" :: "r"(mbar), "r"(cnt) : "memory");
}
__device__ __forceinline__ void mbar_expect(uint32_t mbar, uint32_t bytes){
    asm volatile("mbarrier.arrive.expect_tx.shared.b64 _, [%0], %1;"
                 :: "r"(mbar), "r"(bytes) : "memory");
}
__device__ __forceinline__ void mbar_arrive(uint32_t mbar){
    asm volatile("mbarrier.arrive.shared.b64 _, [%0];" :: "r"(mbar) : "memory");
}
__device__ __forceinline__ void mbar_wait(uint32_t mbar, uint32_t parity){
    asm volatile(
        "{\n\t.reg .pred P1;\n"
        "LW%=:\n\t"
        "mbarrier.try_wait.parity.acquire.cta.shared::cta.b64 P1, [%0], %1, 0x989680;\n\t"
        "@P1 bra LD%=;\n\t"
        "bra LW%=;\n"
        "LD%=:\n\t}"
        :: "r"(mbar), "r"(parity) : "memory");
}
__device__ __forceinline__ void mma16(float* c, const uint32_t* a, uint32_t b0, uint32_t b1){
    asm volatile("mma.sync.aligned.m16n8k16.row.col.f32.f16.f16.f32 "
        "{%0,%1,%2,%3},{%4,%5,%6,%7},{%8,%9},{%0,%1,%2,%3};\n"
        : "+f"(c[0]),"+f"(c[1]),"+f"(c[2]),"+f"(c[3])
        : "r"(a[0]),"r"(a[1]),"r"(a[2]),"r"(a[3]),"r"(b0),"r"(b1));
}
__device__ __forceinline__ void ldm4(uint32_t* r, uint32_t addr){
    asm volatile("ldmatrix.sync.aligned.m8n8.x4.shared.b16 {%0,%1,%2,%3}, [%4];"
        : "=r"(r[0]),"=r"(r[1]),"=r"(r[2]),"=r"(r[3]) : "r"(addr));
}
__device__ __forceinline__ void ldm4t(uint32_t* r, uint32_t addr){
    asm volatile("ldmatrix.sync.aligned.m8n8.x4.trans.shared.b16 {%0,%1,%2,%3}, [%4];"
        : "=r"(r[0]),"=r"(r[1]),"=r"(r[2]),"=r"(r[3]) : "r"(addr));
}

// ---------------------------------------------------------------------------
// Fused QKV weight convert + bias pack + count zero (single launch).
// ---------------------------------------------------------------------------
#define QKV_W4 (Dz*QKVN/4)
__global__ __launch_bounds__(256) void cvt_qkv(
    const float* __restrict__ wq, const float* __restrict__ wk,
    const float* __restrict__ wv,
    const float* __restrict__ bq, const float* __restrict__ bk,
    const float* __restrict__ bv,
    __half* __restrict__ out, float* __restrict__ qkvb, int* __restrict__ cnt)
{
    int i = blockIdx.x * 256 + threadIdx.x;
    if (i < QKV_W4) {
        int row = i / (QKVN/4);
        int c4  = (i - row * (QKVN/4)) * 4;
        const float* src;
        float scale = 1.f;
        if (c4 < 512)       { src = wq + (size_t)row*512  + c4;         scale = 0.125f; }
        else if (c4 < 1536) { src = wk + (size_t)row*1024 + (c4-512);  }
        else                { src = wv + (size_t)row*1024 + (c4-1536); }
        float4 a = *(const float4*)src;
        __half2 h0 = __floats2half2_rn(a.x*scale, a.y*scale);
        __half2 h1 = __floats2half2_rn(a.z*scale, a.w*scale);
        uint2 u; u.x = *(uint32_t*)&h0; u.y = *(uint32_t*)&h1;
        *(uint2*)(out + (size_t)row * QKVN + c4) = u;
    } else {
        int j = i - QKV_W4;
        if (j < 512)        qkvb[j] = bq[j] * 0.125f;
        else if (j < 1536)  qkvb[j] = bk[j - 512];
        else if (j < QKVN)  qkvb[j] = bv[j - 1536];
        else if (j < QKVN + Ez) cnt[j - QKVN] = 0;
    }
}

// ---------------------------------------------------------------------------
// Mega convert: wo + gw1 (hi/lo split) + ew1 + ew2 in ONE launch.
// ---------------------------------------------------------------------------
#define WO4  (Dz*Dz/4)
#define GW4  (Dz*GHz/4)
#define EW4  ((int)((size_t)Ez*Dz*EDz/4))
#define REST_TOTAL (WO4 + GW4 + 2*EW4)
__global__ __launch_bounds__(256) void cvt_rest(
    const float* __restrict__ wo,  __half* __restrict__ woh,
    const float* __restrict__ gw1, __half* __restrict__ gw1h, __half* __restrict__ gw1l,
    const float* __restrict__ ew1, __half* __restrict__ ew1h,
    const float* __restrict__ ew2, __half* __restrict__ ew2h)
{
    int i = blockIdx.x * 256 + threadIdx.x;
    if (i >= REST_TOTAL) return;
    if (i < WO4) {
        float4 a = ((const float4*)wo)[i];
        __half2 h0 = __floats2half2_rn(a.x, a.y);
        __half2 h1 = __floats2half2_rn(a.z, a.w);
        uint2 u; u.x = *(uint32_t*)&h0; u.y = *(uint32_t*)&h1;
        ((uint2*)woh)[i] = u;
    } else if (i < WO4 + GW4) {
        int k = i - WO4;
        float4 a = ((const float4*)gw1)[k];
        __half hx = __float2half_rn(a.x), hy = __float2half_rn(a.y);
        __half hz = __float2half_rn(a.z), hw = __float2half_rn(a.w);
        __half2 H0; H0.x = hx; H0.y = hy;
        __half2 H1; H1.x = hz; H1.y = hw;
        __half2 L0 = __floats2half2_rn(a.x - __half2float(hx), a.y - __half2float(hy));
        __half2 L1 = __floats2half2_rn(a.z - __half2float(hz), a.w - __half2float(hw));
        uint2 uh; uh.x = *(uint32_t*)&H0; uh.y = *(uint32_t*)&H1;
        uint2 ul; ul.x = *(uint32_t*)&L0; ul.y = *(uint32_t*)&L1;
        ((uint2*)gw1h)[k] = uh;
        ((uint2*)gw1l)[k] = ul;
    } else {
        const float* in; __half* o; int k;
        if (i < WO4 + GW4 + EW4) { in = ew1; o = ew1h; k = i - WO4 - GW4; }
        else                     { in = ew2; o = ew2h; k = i - WO4 - GW4 - EW4; }
        float4 a = ((const float4*)in)[k];
        __half2 h0 = __floats2half2_rn(a.x, a.y);
        __half2 h1 = __floats2half2_rn(a.z, a.w);
        uint2 u; u.x = *(uint32_t*)&h0; u.y = *(uint32_t*)&h1;
        ((uint2*)o)[k] = u;
    }
}

// ---------------------------------------------------------------------------
// LayerNorm: one block per token row of 1024.
// ---------------------------------------------------------------------------
template<bool SPLIT>
__global__ __launch_bounds__(256) void ln_kernel(
    const float* __restrict__ X, const float* __restrict__ g,
    const float* __restrict__ b, __half* __restrict__ O16, __half* __restrict__ OLO)
{
    int t = blockIdx.x;
    int tid = threadIdx.x;
    const float4* x4 = (const float4*)(X + (size_t)t * Dz);
    float4 xv = x4[tid];
    float s  = xv.x + xv.y + xv.z + xv.w;
    float ss = xv.x*xv.x + xv.y*xv.y + xv.z*xv.z + xv.w*xv.w;
    #pragma unroll
    for (int off = 16; off; off >>= 1) {
        s  += __shfl_xor_sync(0xffffffffu, s,  off);
        ss += __shfl_xor_sync(0xffffffffu, ss, off);
    }
    __shared__ float sh_s[8], sh_ss[8];
    if ((tid & 31) == 0) { sh_s[tid >> 5] = s; sh_ss[tid >> 5] = ss; }
    __syncthreads();
    if (tid < 32) {
        float a = (tid < 8) ? sh_s[tid]  : 0.f;
        float c = (tid < 8) ? sh_ss[tid] : 0.f;
        #pragma unroll
        for (int off = 4; off; off >>= 1) {
            a += __shfl_xor_sync(0xffffffffu, a, off);
            c += __shfl_xor_sync(0xffffffffu, c, off);
        }
        if (tid == 0) { sh_s[0] = a; sh_ss[0] = c; }
    }
    __syncthreads();
    float mu  = sh_s[0]  * (1.f / Dz);
    float var = sh_ss[0] * (1.f / Dz) - mu * mu;
    float inv = rsqrtf(var + 1e-5f);
    float4 gv = ((const float4*)g)[tid];
    float4 bv = ((const float4*)b)[tid];
    float4 o;
    o.x = (xv.x - mu) * inv * gv.x + bv.x;
    o.y = (xv.y - mu) * inv * gv.y + bv.y;
    o.z = (xv.z - mu) * inv * gv.z + bv.z;
    o.w = (xv.w - mu) * inv * gv.w + bv.w;
    __half hx = __float2half_rn(o.x), hy = __float2half_rn(o.y);
    __half hz = __float2half_rn(o.z), hw = __float2half_rn(o.w);
    __half2 p0; p0.x = hx; p0.y = hy;
    __half2 p1; p1.x = hz; p1.y = hw;
    uint2 u; u.x = *(uint32_t*)&p0; u.y = *(uint32_t*)&p1;
    ((uint2*)(O16 + (size_t)t * Dz))[tid] = u;
    if (SPLIT) {
        __half2 l0 = __floats2half2_rn(o.x - __half2float(hx), o.y - __half2float(hy));
        __half2 l1 = __floats2half2_rn(o.z - __half2float(hz), o.w - __half2float(hw));
        uint2 ul; ul.x = *(uint32_t*)&l0; ul.y = *(uint32_t*)&l1;
        ((uint2*)(OLO + (size_t)t * Dz))[tid] = ul;
    }
}

// ---------------------------------------------------------------------------
// fp16 tensor-core GEMM with cp.async.bulk staging (LSU-issue relief).
// C[M,N] = act(A @ B + bias)(+resid).
// GMODE: 0 dense; 2 A gathered via elist (>>ashift), C dense at e*Tz+m;
//        3 A dense at e*Tz+m, C scattered via elist.
// BM=128, BN=128, BK=64 halves, 256 threads, warp 64x32.
// Staging: per k-tile, threads 0-127 bulk-copy one A row (128 B) each,
// threads 128-191 one B row (256 B) each; mbarrier count=192, tx-bytes.
// 3-stage ring; __syncthreads before re-staging a stage.
// smem: 32 B mbarriers | A[3][128 rows x 144 B] | B[3][64 rows x 272 B].
// ---------------------------------------------------------------------------
#define GEMMH_SMEM (32 + 3*128*144 + 3*64*272)
template<int ACT, int GMODE, bool RESID, bool OUTH>
__global__ void __launch_bounds__(256,2) gemm_hc(
    const __half* __restrict__ A, const __half* __restrict__ B,
    const float* __restrict__ bias, void* __restrict__ Cv,
    int M, int N, int K,
    const float* __restrict__ resid,
    const int* __restrict__ elist, const int* __restrict__ cnt, int ashift)
{
    extern __shared__ __align__(16) char smraw[];
    uint32_t sb = s2u(smraw);
    uint32_t mb = sb;                       // 3 mbarriers (8 B each)
    uint32_t Au = sb + 32;
    uint32_t Bu = Au + 3*128*144;
    const uint32_t abuf = 128*144, bbuf = 64*272;

    int e = blockIdx.z;
    const __half* Bp = B + (size_t)e * K * N;
    const float*  bp = bias + (size_t)e * N;
    int mcount = (GMODE != 0) ? cnt[e] : M;
    int m0 = blockIdx.y * 128;
    if (m0 >= mcount) return;
    int n0 = blockIdx.x * 128;
    const int* lst = (GMODE != 0) ? (elist + e * Tz) : (const int*)nullptr;

    int tid = threadIdx.x;
    int lane = tid & 31, wid = tid >> 5;
    int warpM = wid >> 2, warpN = wid & 3;

    if (tid == 0) {
        mbar_init(mb, 192); mbar_init(mb + 8, 192); mbar_init(mb + 16, 192);
    }
    __syncthreads();

    // staging roles
    const __half* arow = nullptr; bool av = false; uint32_t ad = 0;
    const __half* brow = nullptr; uint32_t bd = 0;
    if (tid < 128) {
        int m = m0 + tid;
        av = (m < mcount);
        size_t rowg;
        if (GMODE == 2)      rowg = av ? (size_t)(lst[m] >> ashift) : 0;
        else if (GMODE == 3) rowg = av ? (size_t)(e * Tz + m) : 0;
        else                 rowg = av ? (size_t)m : 0;
        arow = A + rowg * (size_t)K;
        ad = Au + (uint32_t)tid * 144;
    } else if (tid < 192) {
        int r = tid - 128;
        brow = Bp + (size_t)r * N + n0;
        bd = Bu + (uint32_t)r * 272;
    }

    auto stage = [&](int kt2, int s){
        uint32_t m_ = mb + (uint32_t)s * 8;
        if (tid < 128) {
            if (av) { mbar_expect(m_, 128); cpbulk(ad + (uint32_t)s*abuf, arow + kt2*64, 128, m_); }
            else    { mbar_arrive(m_); }
        } else if (tid < 192) {
            mbar_expect(m_, 256);
            cpbulk(bd + (uint32_t)s*bbuf, brow + (size_t)(kt2*64)*N, 256, m_);
        }
    };

    float acc[4][4][4];
    #pragma unroll
    for (int i=0;i<4;i++)
        #pragma unroll
        for (int j=0;j<4;j++)
            #pragma unroll
            for (int l=0;l<4;l++) acc[i][j][l] = 0.f;

    int KT = K / 64;
    stage(0, 0); stage(1, 1); stage(2, 2);

    uint32_t lr = lane & 15, lc = (lane >> 4) * 8;
    for (int kt = 0; kt < KT; kt++) {
        int s = kt % 3;
        mbar_wait(mb + (uint32_t)s*8, (uint32_t)((kt/3) & 1));

        uint32_t abase = Au + (uint32_t)s*abuf + ((warpM*64 + lr)*72 + lc)*2;
        uint32_t bbase = Bu + (uint32_t)s*bbuf + (lr*136 + warpN*32 + lc)*2;
        #pragma unroll
        for (int ks = 0; ks < 4; ks++) {
            uint32_t ah[4][4];
            #pragma unroll
            for (int mt = 0; mt < 4; mt++)
                ldm4(ah[mt], abase + (mt*16*72 + ks*16)*2);
            uint32_t bt[2][4];
            #pragma unroll
            for (int pr = 0; pr < 2; pr++)
                ldm4t(bt[pr], bbase + (ks*16*136 + pr*16)*2);
            #pragma unroll
            for (int mt = 0; mt < 4; mt++) {
                mma16(acc[mt][0], ah[mt], bt[0][0], bt[0][1]);
                mma16(acc[mt][1], ah[mt], bt[0][2], bt[0][3]);
                mma16(acc[mt][2], ah[mt], bt[1][0], bt[1][1]);
                mma16(acc[mt][3], ah[mt], bt[1][2], bt[1][3]);
            }
        }
        __syncthreads();
        if (kt + 3 < KT) stage(kt + 3, s);
    }

    float2 bv[4];
    #pragma unroll
    for (int nt = 0; nt < 4; nt++)
        bv[nt] = *(const float2*)(bp + n0 + warpN*32 + (lane&3)*2 + nt*8);

    float*  Cf = (float*)Cv;
    __half* Ch = (__half*)Cv;
    #pragma unroll
    for (int mt = 0; mt < 4; mt++) {
        #pragma unroll
        for (int hf = 0; hf < 2; hf++) {
            int r = m0 + warpM*64 + mt*16 + (lane>>2) + hf*8;
            if (r >= mcount) continue;
            size_t crow;
            if (GMODE == 2)      crow = (size_t)(e * Tz + r);
            else if (GMODE == 3) crow = (size_t)lst[r];
            else                 crow = (size_t)r;
            int coff = n0 + warpN*32 + (lane&3)*2;
            const float* Rr = RESID ? (resid + crow*(size_t)N + coff) : (const float*)nullptr;
            #pragma unroll
            for (int nt = 0; nt < 4; nt++) {
                float v0 = acc[mt][nt][hf*2+0] + bv[nt].x;
                float v1 = acc[mt][nt][hf*2+1] + bv[nt].y;
                if (ACT == 1) { v0 = fmaxf(v0, 0.f); v1 = fmaxf(v1, 0.f); }
                if (ACT == 2) {
                    v0 = 0.5f*v0*(1.f + erff(v0*0.70710678118654752f));
                    v1 = 0.5f*v1*(1.f + erff(v1*0.70710678118654752f));
                }
                if (RESID) { v0 += Rr[nt*8]; v1 += Rr[nt*8+1]; }
                if (OUTH) {
                    __half2 h = __floats2half2_rn(v0, v1);
                    *(__half2*)(Ch + crow*(size_t)N + coff + nt*8) = h;
                } else {
                    float2 o; o.x = v0; o.y = v1;
                    *(float2*)(Cf + crow*(size_t)N + coff + nt*8) = o;
                }
            }
        }
    }
}

// ---------------------------------------------------------------------------
// Split-fp16 gate GEMM (near-fp32), cp.async staging (control / unchanged).
// ---------------------------------------------------------------------------
#define GATE_SMEM (2*2*128*40*2 + 2*2*32*136*2)
__global__ void __launch_bounds__(256,2) gemm_gate16(
    const __half* __restrict__ Ah, const __half* __restrict__ Al,
    const __half* __restrict__ Bh, const __half* __restrict__ Bl,
    const float* __restrict__ bias, float* __restrict__ C,
    int M, int N, int K)
{
    extern __shared__ __half smh[];
    __half* Ahs = smh;                        // [2][128][40]
    __half* Als = Ahs + 2*128*40;             // [2][128][40]
    __half* Bhs = Als + 2*128*40;             // [2][32][136]
    __half* Bls = Bhs + 2*32*136;             // [2][32][136]

    int m0 = blockIdx.y * 128;
    int n0 = blockIdx.x * 128;
    int tid = threadIdx.x;
    int lane = tid & 31, wid = tid >> 5;
    int warpM = wid >> 2, warpN = wid & 3;

    int arow = tid >> 1, acol = (tid & 1) * 16;
    const __half* ahp = Ah + (size_t)(m0 + arow) * K + acol;
    const __half* alp = Al + (size_t)(m0 + arow) * K + acol;
    uint32_t ahd = s2u(&Ahs[arow * 40 + acol]);
    uint32_t ald = s2u(&Als[arow * 40 + acol]);
    int brow = tid >> 3, bcol = (tid & 7) * 16;
    const __half* bhp = Bh + (size_t)brow * N + n0 + bcol;
    const __half* blp = Bl + (size_t)brow * N + n0 + bcol;
    uint32_t bhd = s2u(&Bhs[brow * 136 + bcol]);
    uint32_t bld = s2u(&Bls[brow * 136 + bcol]);

    const uint32_t abuf = 128*40*2, bbuf = 32*136*2;

    auto stage = [&](int kt, int buf){
        int k0 = kt * 32;
        cpa16(ahd + buf*abuf,      ahp + k0, true);
        cpa16(ahd + buf*abuf + 16, ahp + k0 + 8, true);
        cpa16(ald + buf*abuf,      alp + k0, true);
        cpa16(ald + buf*abuf + 16, alp + k0 + 8, true);
        cpa16(bhd + buf*bbuf,      bhp + (size_t)k0*N, true);
        cpa16(bhd + buf*bbuf + 16, bhp + (size_t)k0*N + 8, true);
        cpa16(bld + buf*bbuf,      blp + (size_t)k0*N, true);
        cpa16(bld + buf*bbuf + 16, blp + (size_t)k0*N + 8, true);
    };

    uint32_t ahs_u = s2u(Ahs), als_u = s2u(Als);
    uint32_t bhs_u = s2u(Bhs), bls_u = s2u(Bls);

    float acc[4][4][4];
    #pragma unroll
    for (int i=0;i<4;i++)
        #pragma unroll
        for (int j=0;j<4;j++)
            #pragma unroll
            for (int l=0;l<4;l++) acc[i][j][l] = 0.f;

    int KT = K / 32;
    stage(0, 0); cp_commit();

    uint32_t lr = lane & 15, lc = (lane >> 4) * 8;
    for (int kt = 0; kt < KT; kt++) {
        int buf = kt & 1;
        cp_wait0();
        __syncthreads();
        if (kt + 1 < KT) { stage(kt+1, buf ^ 1); }
        cp_commit();

        uint32_t aoff = ((uint32_t)buf*(128*40) + (warpM*64 + lr)*40 + lc)*2;
        uint32_t boff = ((uint32_t)buf*(32*136) + lr*136 + warpN*32 + lc)*2;
        #pragma unroll
        for (int ks = 0; ks < 2; ks++) {
            uint32_t ah[4][4], al[4][4];
            #pragma unroll
            for (int mt = 0; mt < 4; mt++) {
                ldm4(ah[mt], ahs_u + aoff + (mt*16*40 + ks*16)*2);
                ldm4(al[mt], als_u + aoff + (mt*16*40 + ks*16)*2);
            }
            uint32_t bth[2][4], btl[2][4];
            #pragma unroll
            for (int pr = 0; pr < 2; pr++) {
                ldm4t(bth[pr], bhs_u + boff + (ks*16*136 + pr*16)*2);
                ldm4t(btl[pr], bls_u + boff + (ks*16*136 + pr*16)*2);
            }
            #pragma unroll
            for (int mt = 0; mt < 4; mt++) {
                mma16(acc[mt][0], ah[mt], bth[0][0], bth[0][1]);
                mma16(acc[mt][1], ah[mt], bth[0][2], bth[0][3]);
                mma16(acc[mt][2], ah[mt], bth[1][0], bth[1][1]);
                mma16(acc[mt][3], ah[mt], bth[1][2], bth[1][3]);
                mma16(acc[mt][0], al[mt], bth[0][0], bth[0][1]);
                mma16(acc[mt][1], al[mt], bth[0][2], bth[0][3]);
                mma16(acc[mt][2], al[mt], bth[1][0], bth[1][1]);
                mma16(acc[mt][3], al[mt], bth[1][2], bth[1][3]);
                mma16(acc[mt][0], ah[mt], btl[0][0], btl[0][1]);
                mma16(acc[mt][1], ah[mt], btl[0][2], btl[0][3]);
                mma16(acc[mt][2], ah[mt], btl[1][0], btl[1][1]);
                mma16(acc[mt][3], ah[mt], btl[1][2], btl[1][3]);
            }
        }
    }

    float2 bv[4];
    #pragma unroll
    for (int nt = 0; nt < 4; nt++)
        bv[nt] = *(const float2*)(bias + n0 + warpN*32 + (lane&3)*2 + nt*8);

    #pragma unroll
    for (int mt = 0; mt < 4; mt++)
        #pragma unroll
        for (int hf = 0; hf < 2; hf++) {
            int r = m0 + warpM*64 + mt*16 + (lane>>2) + hf*8;
            float* Cr = C + (size_t)r*N + n0 + warpN*32 + (lane&3)*2;
            #pragma unroll
            for (int nt = 0; nt < 4; nt++) {
                float v0 = fmaxf(acc[mt][nt][hf*2+0] + bv[nt].x, 0.f);
                float v1 = fmaxf(acc[mt][nt][hf*2+1] + bv[nt].y, 0.f);
                float2 o; o.x = v0; o.y = v1;
                *(float2*)(Cr + nt*8) = o;
            }
        }
}

// ---------------------------------------------------------------------------
// Fused flash attention; K/V staged via cp.async.bulk + mbarrier (2-stage),
// Q via cp.async (one-shot). fp16 mma.sync, online softmax.
// smem: 32 B mbarriers | Ps[128 rows x 272 B] (alias Q rows 144 B) |
//       K[2][128x144 B] | V[2][128x144 B]
// ---------------------------------------------------------------------------
#define FA_SMEM (32 + 128*272 + 4*128*144)
__global__ void __launch_bounds__(256,2) fa_h(
    const __half* __restrict__ QKV, __half* __restrict__ O)
{
    extern __shared__ __align__(16) char smraw[];
    uint32_t sb = s2u(smraw);
    uint32_t mbr = sb;                 // 2 mbarriers
    uint32_t Pu  = sb + 32;            // [128][136] halves
    uint32_t Ku  = Pu + 128*272;       // [2][128][72] halves
    uint32_t Vu  = Ku + 2*128*144;
    const uint32_t kvbuf = 128*144;

    int bh = blockIdx.y, b = bh >> 4, h = bh & 15, g = h >> 1;
    int q0 = blockIdx.x * 128;
    int tid = threadIdx.x, lane = tid & 31, w = tid >> 5;

    if (tid == 0) { mbar_init(mbr, 256); mbar_init(mbr + 8, 256); }
    __syncthreads();

    // Q staging (cp.async, one group)
    const __half* Qb = QKV + (size_t)(b*Sz + q0) * QKVN + g*64;
    {
        int row = tid >> 1;
        #pragma unroll
        for (int j = 0; j < 4; j++) {
            int c = (tid & 1) + 2*j;
            cpa16(Pu + (uint32_t)row*144 + (uint32_t)c*16, Qb + (size_t)row*QKVN + c*8, true);
        }
    }
    cp_commit();

    // K/V bulk staging: thread<128 -> K row tid, else V row tid-128 (128 B each)
    const __half* Kb = QKV + (size_t)(b*Sz)*QKVN + 512 + h*64;
    const __half* Vb = QKV + (size_t)(b*Sz)*QKVN + 1536 + h*64;
    const __half* kvrow;
    uint32_t kvd;
    if (tid < 128) { kvrow = Kb + (size_t)tid*QKVN;        kvd = Ku + (uint32_t)tid*144; }
    else           { kvrow = Vb + (size_t)(tid-128)*QKVN;  kvd = Vu + (uint32_t)(tid-128)*144; }

    auto stageKV = [&](int kt, int s){
        uint32_t m_ = mbr + (uint32_t)s*8;
        mbar_expect(m_, 128);
        cpbulk(kvd + (uint32_t)s*kvbuf, kvrow + (size_t)(kt*128)*QKVN, 128, m_);
    };
    stageKV(0, 0);
    stageKV(1, 1);

    cp_wait0();
    __syncthreads();
    uint32_t lr = lane & 15, lc = (lane >> 4) * 8;
    uint32_t qbase = Pu + ((w*16 + lr)*72 + lc)*2;
    uint32_t qf[4][4];
    #pragma unroll
    for (int ks = 0; ks < 4; ks++) ldm4(qf[ks], qbase + ks*32);
    __syncthreads();   // Ps region reusable for P

    float m0 = -INFINITY, m1 = -INFINITY, l0 = 0.f, l1 = 0.f;
    float oacc[8][4];
    #pragma unroll
    for (int i=0;i<8;i++)
        #pragma unroll
        for (int j=0;j<4;j++) oacc[i][j] = 0.f;

    uint32_t pabase = Pu + ((w*16 + lr)*136 + lc)*2;
    uint32_t prow_u = Pu + ((w*16 + (lane>>2))*136 + (lane&3)*2)*2;
    __half* prow = (__half*)(smraw + (prow_u - sb));

    for (int kt = 0; kt < 8; kt++) {
        int s = kt & 1;
        mbar_wait(mbr + (uint32_t)s*8, (uint32_t)((kt >> 1) & 1));

        // ---- S = Q @ K^T ----
        float sacc[16][4];
        #pragma unroll
        for (int i=0;i<16;i++)
            #pragma unroll
            for (int j=0;j<4;j++) sacc[i][j] = 0.f;
        uint32_t kbase = Ku + (uint32_t)s*kvbuf + (lr*72 + lc)*2;
        #pragma unroll
        for (int ks = 0; ks < 4; ks++) {
            #pragma unroll
            for (int np = 0; np < 8; np++) {
                uint32_t r[4];
                ldm4(r, kbase + (np*16*72 + ks*16)*2);
                mma16(sacc[2*np  ], qf[ks], r[0], r[2]);
                mma16(sacc[2*np+1], qf[ks], r[1], r[3]);
            }
        }

        // ---- online softmax ----
        float t0 = -INFINITY, t1 = -INFINITY;
        #pragma unroll
        for (int nt = 0; nt < 16; nt++) {
            t0 = fmaxf(t0, fmaxf(sacc[nt][0], sacc[nt][1]));
            t1 = fmaxf(t1, fmaxf(sacc[nt][2], sacc[nt][3]));
        }
        t0 = fmaxf(t0, __shfl_xor_sync(0xffffffffu, t0, 1));
        t0 = fmaxf(t0, __shfl_xor_sync(0xffffffffu, t0, 2));
        t1 = fmaxf(t1, __shfl_xor_sync(0xffffffffu, t1, 1));
        t1 = fmaxf(t1, __shfl_xor_sync(0xffffffffu, t1, 2));
        float mn0 = fmaxf(m0, t0), mn1 = fmaxf(m1, t1);
        float sc0 = __expf(m0 - mn0), sc1 = __expf(m1 - mn1);
        float s0 = 0.f, s1 = 0.f;
        #pragma unroll
        for (int nt = 0; nt < 16; nt++) {
            sacc[nt][0] = __expf(sacc[nt][0] - mn0);
            sacc[nt][1] = __expf(sacc[nt][1] - mn0);
            sacc[nt][2] = __expf(sacc[nt][2] - mn1);
            sacc[nt][3] = __expf(sacc[nt][3] - mn1);
            s0 += sacc[nt][0] + sacc[nt][1];
            s1 += sacc[nt][2] + sacc[nt][3];
        }
        s0 += __shfl_xor_sync(0xffffffffu, s0, 1);
        s0 += __shfl_xor_sync(0xffffffffu, s0, 2);
        s1 += __shfl_xor_sync(0xffffffffu, s1, 1);
        s1 += __shfl_xor_sync(0xffffffffu, s1, 2);
        l0 = l0*sc0 + s0; l1 = l1*sc1 + s1;
        m0 = mn0; m1 = mn1;
        #pragma unroll
        for (int nt = 0; nt < 8; nt++) {
            oacc[nt][0] *= sc0; oacc[nt][1] *= sc0;
            oacc[nt][2] *= sc1; oacc[nt][3] *= sc1;
        }

        // ---- P -> smem fp16 (own rows only) ----
        #pragma unroll
        for (int nt = 0; nt < 16; nt++) {
            *(__half2*)(prow + nt*8)          = __floats2half2_rn(sacc[nt][0], sacc[nt][1]);
            *(__half2*)(prow + 8*136 + nt*8)  = __floats2half2_rn(sacc[nt][2], sacc[nt][3]);
        }
        __syncwarp();

        // ---- O += P @ V ----
        uint32_t vbase = Vu + (uint32_t)s*kvbuf + (lr*72 + lc)*2;
        #pragma unroll
        for (int k2 = 0; k2 < 8; k2++) {
            uint32_t pf[4];
            ldm4(pf, pabase + k2*32);
            #pragma unroll
            for (int hp = 0; hp < 4; hp++) {
                uint32_t vt[4];
                ldm4t(vt, vbase + (k2*16*72 + hp*16)*2);
                mma16(oacc[2*hp  ], pf, vt[0], vt[1]);
                mma16(oacc[2*hp+1], pf, vt[2], vt[3]);
            }
        }

        __syncthreads();
        if (kt + 2 < 8) stageKV(kt + 2, s);
    }

    float i0 = 1.f / l0, i1 = 1.f / l1;
    int r0 = q0 + w*16 + (lane >> 2);
    __half* Op = O + (size_t)(b*Sz + r0)*1024 + h*64 + (lane&3)*2;
    #pragma unroll
    for (int nt = 0; nt < 8; nt++) {
        *(__half2*)(Op + nt*8)          = __floats2half2_rn(oacc[nt][0]*i0, oacc[nt][1]*i0);
        *(__half2*)(Op + 8*1024 + nt*8) = __floats2half2_rn(oacc[nt][2]*i1, oacc[nt][3]*i1);
    }
}

// ---------------------------------------------------------------------------
// Gate head + softmax + top-2 + renorm + routing. One warp per token.
// ---------------------------------------------------------------------------
__global__ __launch_bounds__(256) void gate_route_kernel(
    const float* __restrict__ GH, const float* __restrict__ gw2,
    const float* __restrict__ gb2,
    float* __restrict__ wout, int* __restrict__ cnt, int* __restrict__ elist)
{
    int warp = threadIdx.x >> 5;
    int lane = threadIdx.x & 31;
    int t = blockIdx.x * 8 + warp;
    if (t >= Tz) return;

    float logit[Ez];
    #pragma unroll
    for (int o = 0; o < Ez; o++) {
        float s = 0.f;
        for (int i = lane; i < GHz; i += 32)
            s += GH[(size_t)t * GHz + i] * gw2[(size_t)i * Ez + o];
        #pragma unroll
        for (int off = 16; off; off >>= 1)
            s += __shfl_xor_sync(0xffffffffu, s, off);
        logit[o] = s + gb2[o];
    }
    if (lane == 0) {
        float m = logit[0];
        #pragma unroll
        for (int o = 1; o < Ez; o++) m = fmaxf(m, logit[o]);
        float w[Ez], sum = 0.f;
        #pragma unroll
        for (int o = 0; o < Ez; o++) { w[o] = expf(logit[o] - m); sum += w[o]; }
        float invs = 1.f / sum;
        #pragma unroll
        for (int o = 0; o < Ez; o++) w[o] *= invs;
        int i0 = 0; float v0 = w[0];
        #pragma unroll
        for (int o = 1; o < Ez; o++) if (w[o] > v0) { v0 = w[o]; i0 = o; }
        int i1 = -1; float v1 = -1.f;
        #pragma unroll
        for (int o = 0; o < Ez; o++)
            if (o != i0 && w[o] > v1) { v1 = w[o]; i1 = o; }
        float e1 = expf(v1 - v0);
        float den = 1.f + e1;
        wout[2*t + 0] = 1.f / den;
        wout[2*t + 1] = e1 / den;
        int p0 = atomicAdd(&cnt[i0], 1);
        elist[i0 * Tz + p0] = 2*t + 0;
        int p1 = atomicAdd(&cnt[i1], 1);
        elist[i1 * Tz + p1] = 2*t + 1;
    }
}

// ---------------------------------------------------------------------------
// Final combine: out = x1 + w0*eo[2t] + w1*eo[2t+1]  (eo fp16)
// ---------------------------------------------------------------------------
__global__ __launch_bounds__(256) void combine_kernel(
    const float* __restrict__ x1, const __half* __restrict__ eo,
    const float* __restrict__ w, float* __restrict__ out)
{
    int idx = blockIdx.x * 256 + threadIdx.x;
    int t = idx >> 8;
    int c = idx & 255;
    float w0 = w[2*t], w1 = w[2*t + 1];
    float4 a  = ((const float4*)x1)[idx];
    uint2 u0 = ((const uint2*)(eo + (size_t)(2*t)     * Dz))[c];
    uint2 u1 = ((const uint2*)(eo + (size_t)(2*t + 1) * Dz))[c];
    float2 e0a = __half22float2(*(__half2*)&u0.x);
    float2 e0b = __half22float2(*(__half2*)&u0.y);
    float2 e1a = __half22float2(*(__half2*)&u1.x);
    float2 e1b = __half22float2(*(__half2*)&u1.y);
    float4 r;
    r.x = a.x + w0 * e0a.x + w1 * e1a.x;
    r.y = a.y + w0 * e0a.y + w1 * e1a.y;
    r.z = a.z + w0 * e0b.x + w1 * e1b.x;
    r.w = a.w + w0 * e0b.y + w1 * e1b.y;
    ((float4*)out)[idx] = r;
}

// ---------------------------------------------------------------------------
// Host launch (single stream — graph-capture safe)
// ---------------------------------------------------------------------------
extern "C" void kernel_launch(void* const* d_in, const int* in_sizes, int n_in,
                              void* d_out, int out_size)
{
    const float* x    = (const float*)d_in[0];
    const float* wq   = (const float*)d_in[1];
    const float* bq   = (const float*)d_in[2];
    const float* wk   = (const float*)d_in[3];
    const float* bk   = (const float*)d_in[4];
    const float* wv   = (const float*)d_in[5];
    const float* bv   = (const float*)d_in[6];
    const float* wo   = (const float*)d_in[7];
    const float* bo   = (const float*)d_in[8];
    const float* ln1g = (const float*)d_in[9];
    const float* ln1b = (const float*)d_in[10];
    const float* ln2g = (const float*)d_in[11];
    const float* ln2b = (const float*)d_in[12];
    const float* gw1  = (const float*)d_in[13];
    const float* gb1  = (const float*)d_in[14];
    const float* gw2  = (const float*)d_in[15];
    const float* gb2  = (const float*)d_in[16];
    const float* ew1  = (const float*)d_in[17];
    const float* eb1  = (const float*)d_in[18];
    const float* ew2  = (const float*)d_in[19];
    const float* eb2  = (const float*)d_in[20];
    float* out = (float*)d_out;

    __half *h1h, *qkvh, *aoh, *h2h, *h2l, *hidh, *eo;
    __half *wqkvh, *woh, *ew1h, *ew2h, *gw1h, *gw1l;
    float *x1, *gh, *w, *qkvb;
    int *cnt, *elist;
    cudaGetSymbolAddress((void**)&h1h,  g_h1h);
    cudaGetSymbolAddress((void**)&qkvh, g_qkvh);
    cudaGetSymbolAddress((void**)&aoh,  g_aoh);
    cudaGetSymbolAddress((void**)&x1,   g_x1);
    cudaGetSymbolAddress((void**)&h2h,  g_h2h);
    cudaGetSymbolAddress((void**)&h2l,  g_h2l);
    cudaGetSymbolAddress((void**)&gh,   g_gh);
    cudaGetSymbolAddress((void**)&w,    g_w);
    cudaGetSymbolAddress((void**)&hidh, g_hidh);
    cudaGetSymbolAddress((void**)&eo,   g_eo);
    cudaGetSymbolAddress((void**)&cnt,  g_cnt);
    cudaGetSymbolAddress((void**)&elist,g_elist);
    cudaGetSymbolAddress((void**)&wqkvh,g_wqkvh);
    cudaGetSymbolAddress((void**)&woh,  g_woh);
    cudaGetSymbolAddress((void**)&ew1h, g_ew1h);
    cudaGetSymbolAddress((void**)&ew2h, g_ew2h);
    cudaGetSymbolAddress((void**)&gw1h, g_gw1h);
    cudaGetSymbolAddress((void**)&gw1l, g_gw1l);
    cudaGetSymbolAddress((void**)&qkvb, g_qkvb);

    cudaFuncSetAttribute(gemm_hc<0,0,false,true>, cudaFuncAttributeMaxDynamicSharedMemorySize, GEMMH_SMEM);
    cudaFuncSetAttribute(gemm_hc<0,0,true,false>, cudaFuncAttributeMaxDynamicSharedMemorySize, GEMMH_SMEM);
    cudaFuncSetAttribute(gemm_hc<2,2,false,true>, cudaFuncAttributeMaxDynamicSharedMemorySize, GEMMH_SMEM);
    cudaFuncSetAttribute(gemm_hc<0,3,false,true>, cudaFuncAttributeMaxDynamicSharedMemorySize, GEMMH_SMEM);
    cudaFuncSetAttribute(gemm_gate16, cudaFuncAttributeMaxDynamicSharedMemorySize, GATE_SMEM);
    cudaFuncSetAttribute(fa_h, cudaFuncAttributeMaxDynamicSharedMemorySize, FA_SMEM);

    // launch 0: fused qkv weight convert + bias pack + count zero
    cvt_qkv<<<(QKV_W4 + QKVN + Ez + 255)/256, 256>>>(
        wq, wk, wv, bq, bk, bv, wqkvh, qkvb, cnt);
    // launch 1: all remaining weight converts in one HBM-bound pass
    cvt_rest<<<(REST_TOTAL + 255)/256, 256>>>(
        wo, woh, gw1, gw1h, gw1l, ew1, ew1h, ew2, ew2h);

    // LN1
    ln_kernel<false><<<Tz, 256>>>(x, ln1g, ln1b, h1h, nullptr);

    // Fused QKV projection
    gemm_hc<0,0,false,true><<<dim3(QKVN/128, 32, 1), 256, GEMMH_SMEM>>>(
        h1h, wqkvh, qkvb, qkvh, Tz, QKVN, Dz, nullptr, nullptr, nullptr, 0);

    fa_h<<<dim3(Sz/128, Bz*Hh), 256, FA_SMEM>>>(qkvh, aoh);

    // Output projection + residual -> x1 fp32
    gemm_hc<0,0,true,false><<<dim3(8, 32, 1), 256, GEMMH_SMEM>>>(
        aoh, woh, bo, x1, Tz, Dz, Dz, x, nullptr, nullptr, 0);

    ln_kernel<true><<<Tz, 256>>>(x1, ln2g, ln2b, h2h, h2l);

    gemm_gate16<<<dim3(GHz/128, Tz/128, 1), 256, GATE_SMEM>>>(
        h2h, h2l, gw1h, gw1l, gb1, gh, Tz, GHz, Dz);

    gate_route_kernel<<<Tz/8, 256>>>(gh, gw2, gb2, w, cnt, elist);

    // Expert FFN: GEMM1 A-gathered / C-dense (hid rows e*Tz+m),
    //             GEMM2 A-dense / C-scattered (eo rows = assignment id)
    gemm_hc<2,2,false,true><<<dim3(EDz/128, Tz/128, Ez), 256, GEMMH_SMEM>>>(
        h2h, ew1h, eb1, hidh, Tz, EDz, Dz, nullptr, elist, cnt, 1);
    gemm_hc<0,3,false,true><<<dim3(Dz/128, Tz/128, Ez), 256, GEMMH_SMEM>>>(
        hidh, ew2h, eb2, eo, Tz, Dz, EDz, nullptr, elist, cnt, 0);

    combine_kernel<<<(Tz*Dz/4)/256, 256>>>(x1, eo, w, out);
}

// round 16
// speedup vs baseline: 1.0830x; 1.0625x over previous
#include <cuda_runtime.h>
#include <cuda_fp16.h>
#include <math.h>
#include <stdint.h>

// ---------------------------------------------------------------------------
// Problem constants
// ---------------------------------------------------------------------------
#define Bz   4
#define Sz   1024
#define Dz   1024
#define Hh   16
#define Gg   8
#define HDz  64
#define Ez   8
#define EDz  2048
#define GHz  512
#define Tz   (Bz*Sz)          // 4096 tokens
#define QKVN 2560             // packed q(512) | k(1024) | v(1024)

// ---------------------------------------------------------------------------
// Scratch (static device memory)
// ---------------------------------------------------------------------------
__device__ __half g_h1h [Tz*Dz];
__device__ __half g_qkvh[(size_t)Tz*QKVN];
__device__ __half g_aoh [Tz*Dz];
__device__ float  g_x1  [Tz*Dz];
__device__ __half g_h2h [Tz*Dz];       // LN2 out, fp16 hi
__device__ __half g_h2l [Tz*Dz];       // LN2 out, fp16 lo (residual)
__device__ float  g_gh  [Tz*GHz];
__device__ float  g_w   [Tz*2];
__device__ int    g_cnt [Ez];
__device__ int    g_elist[Ez*Tz];
__device__ __half g_hidh[(size_t)Ez*Tz*EDz];   // per-expert dense rows (e*Tz + m)
__device__ __half g_eo  [(size_t)Tz*2*Dz];
// fp16 weights ([K][N] row-major; qkv packed) + packed qkv bias
__device__ __half g_wqkvh[(size_t)Dz*QKVN];
__device__ __half g_woh  [(size_t)Dz*Dz];
__device__ __half g_ew1h [(size_t)Ez*Dz*EDz];
__device__ __half g_ew2h [(size_t)Ez*EDz*Dz];
__device__ __half g_gw1h [(size_t)Dz*GHz];   // gate w1 hi
__device__ __half g_gw1l [(size_t)Dz*GHz];   // gate w1 lo
__device__ float  g_qkvb [QKVN];

// ---------------------------------------------------------------------------
// Helpers
// ---------------------------------------------------------------------------
__device__ __forceinline__ uint32_t s2u(const void* p){
    return (uint32_t)__cvta_generic_to_shared(p);
}
__device__ __forceinline__ void cpa16(uint32_t d, const void* s, bool v){
    asm volatile("cp.async.cg.shared.global [%0], [%1], 16, %2;\n"
                 :: "r"(d), "l"(s), "r"(v ? 16 : 0));
}
__device__ __forceinline__ void cp_commit(){ asm volatile("cp.async.commit_group;\n"); }
__device__ __forceinline__ void cp_wait0(){ asm volatile("cp.async.wait_group 0;\n"); }
// Bulk async copy global->shared, completion via mbarrier tx-bytes
__device__ __forceinline__ void cpbulk(uint32_t d, const void* s, uint32_t bytes, uint32_t mbar){
    asm volatile("cp.async.bulk.shared::cluster.global.mbarrier::complete_tx::bytes "
                 "[%0], [%1], %2, [%3];"
                 :: "r"(d), "l"(s), "r"(bytes), "r"(mbar) : "memory");
}
__device__ __forceinline__ void mbar_init(uint32_t mbar, uint32_t cnt){
    asm volatile("mbarrier.init.shared.b64 [%0], %1;" :: "r"(mbar), "r"(cnt) : "memory");
}
__device__ __forceinline__ void mbar_expect(uint32_t mbar, uint32_t bytes){
    asm volatile("mbarrier.arrive.expect_tx.shared.b64 _, [%0], %1;"
                 :: "r"(mbar), "r"(bytes) : "memory");
}
__device__ __forceinline__ void mbar_arrive(uint32_t mbar){
    asm volatile("mbarrier.arrive.shared.b64 _, [%0];" :: "r"(mbar) : "memory");
}
__device__ __forceinline__ void mbar_wait(uint32_t mbar, uint32_t parity){
    asm volatile(
        "{\n\t.reg .pred P1;\n"
        "LW%=:\n\t"
        "mbarrier.try_wait.parity.acquire.cta.shared::cta.b64 P1, [%0], %1, 0x989680;\n\t"
        "@P1 bra LD%=;\n\t"
        "bra LW%=;\n"
        "LD%=:\n\t}"
        :: "r"(mbar), "r"(parity) : "memory");
}
__device__ __forceinline__ void mma16(float* c, const uint32_t* a, uint32_t b0, uint32_t b1){
    asm volatile("mma.sync.aligned.m16n8k16.row.col.f32.f16.f16.f32 "
        "{%0,%1,%2,%3},{%4,%5,%6,%7},{%8,%9},{%0,%1,%2,%3};\n"
        : "+f"(c[0]),"+f"(c[1]),"+f"(c[2]),"+f"(c[3])
        : "r"(a[0]),"r"(a[1]),"r"(a[2]),"r"(a[3]),"r"(b0),"r"(b1));
}
__device__ __forceinline__ void ldm4(uint32_t* r, uint32_t addr){
    asm volatile("ldmatrix.sync.aligned.m8n8.x4.shared.b16 {%0,%1,%2,%3}, [%4];"
        : "=r"(r[0]),"=r"(r[1]),"=r"(r[2]),"=r"(r[3]) : "r"(addr));
}
__device__ __forceinline__ void ldm4t(uint32_t* r, uint32_t addr){
    asm volatile("ldmatrix.sync.aligned.m8n8.x4.trans.shared.b16 {%0,%1,%2,%3}, [%4];"
        : "=r"(r[0]),"=r"(r[1]),"=r"(r[2]),"=r"(r[3]) : "r"(addr));
}

// ---------------------------------------------------------------------------
// Fused QKV weight convert + bias pack + count zero (single launch).
// ---------------------------------------------------------------------------
#define QKV_W4 (Dz*QKVN/4)
__global__ __launch_bounds__(256) void cvt_qkv(
    const float* __restrict__ wq, const float* __restrict__ wk,
    const float* __restrict__ wv,
    const float* __restrict__ bq, const float* __restrict__ bk,
    const float* __restrict__ bv,
    __half* __restrict__ out, float* __restrict__ qkvb, int* __restrict__ cnt)
{
    int i = blockIdx.x * 256 + threadIdx.x;
    if (i < QKV_W4) {
        int row = i / (QKVN/4);
        int c4  = (i - row * (QKVN/4)) * 4;
        const float* src;
        float scale = 1.f;
        if (c4 < 512)       { src = wq + (size_t)row*512  + c4;         scale = 0.125f; }
        else if (c4 < 1536) { src = wk + (size_t)row*1024 + (c4-512);  }
        else                { src = wv + (size_t)row*1024 + (c4-1536); }
        float4 a = *(const float4*)src;
        __half2 h0 = __floats2half2_rn(a.x*scale, a.y*scale);
        __half2 h1 = __floats2half2_rn(a.z*scale, a.w*scale);
        uint2 u; u.x = *(uint32_t*)&h0; u.y = *(uint32_t*)&h1;
        *(uint2*)(out + (size_t)row * QKVN + c4) = u;
    } else {
        int j = i - QKV_W4;
        if (j < 512)        qkvb[j] = bq[j] * 0.125f;
        else if (j < 1536)  qkvb[j] = bk[j - 512];
        else if (j < QKVN)  qkvb[j] = bv[j - 1536];
        else if (j < QKVN + Ez) cnt[j - QKVN] = 0;
    }
}

// ---------------------------------------------------------------------------
// Mega convert: wo + gw1 (hi/lo split) + ew1 + ew2 in ONE launch.
// ---------------------------------------------------------------------------
#define WO4  (Dz*Dz/4)
#define GW4  (Dz*GHz/4)
#define EW4  ((int)((size_t)Ez*Dz*EDz/4))
#define REST_TOTAL (WO4 + GW4 + 2*EW4)
__global__ __launch_bounds__(256) void cvt_rest(
    const float* __restrict__ wo,  __half* __restrict__ woh,
    const float* __restrict__ gw1, __half* __restrict__ gw1h, __half* __restrict__ gw1l,
    const float* __restrict__ ew1, __half* __restrict__ ew1h,
    const float* __restrict__ ew2, __half* __restrict__ ew2h)
{
    int i = blockIdx.x * 256 + threadIdx.x;
    if (i >= REST_TOTAL) return;
    if (i < WO4) {
        float4 a = ((const float4*)wo)[i];
        __half2 h0 = __floats2half2_rn(a.x, a.y);
        __half2 h1 = __floats2half2_rn(a.z, a.w);
        uint2 u; u.x = *(uint32_t*)&h0; u.y = *(uint32_t*)&h1;
        ((uint2*)woh)[i] = u;
    } else if (i < WO4 + GW4) {
        int k = i - WO4;
        float4 a = ((const float4*)gw1)[k];
        __half hx = __float2half_rn(a.x), hy = __float2half_rn(a.y);
        __half hz = __float2half_rn(a.z), hw = __float2half_rn(a.w);
        __half2 H0; H0.x = hx; H0.y = hy;
        __half2 H1; H1.x = hz; H1.y = hw;
        __half2 L0 = __floats2half2_rn(a.x - __half2float(hx), a.y - __half2float(hy));
        __half2 L1 = __floats2half2_rn(a.z - __half2float(hz), a.w - __half2float(hw));
        uint2 uh; uh.x = *(uint32_t*)&H0; uh.y = *(uint32_t*)&H1;
        uint2 ul; ul.x = *(uint32_t*)&L0; ul.y = *(uint32_t*)&L1;
        ((uint2*)gw1h)[k] = uh;
        ((uint2*)gw1l)[k] = ul;
    } else {
        const float* in; __half* o; int k;
        if (i < WO4 + GW4 + EW4) { in = ew1; o = ew1h; k = i - WO4 - GW4; }
        else                     { in = ew2; o = ew2h; k = i - WO4 - GW4 - EW4; }
        float4 a = ((const float4*)in)[k];
        __half2 h0 = __floats2half2_rn(a.x, a.y);
        __half2 h1 = __floats2half2_rn(a.z, a.w);
        uint2 u; u.x = *(uint32_t*)&h0; u.y = *(uint32_t*)&h1;
        ((uint2*)o)[k] = u;
    }
}

// ---------------------------------------------------------------------------
// LayerNorm: one block per token row of 1024.
// ---------------------------------------------------------------------------
template<bool SPLIT>
__global__ __launch_bounds__(256) void ln_kernel(
    const float* __restrict__ X, const float* __restrict__ g,
    const float* __restrict__ b, __half* __restrict__ O16, __half* __restrict__ OLO)
{
    int t = blockIdx.x;
    int tid = threadIdx.x;
    const float4* x4 = (const float4*)(X + (size_t)t * Dz);
    float4 xv = x4[tid];
    float s  = xv.x + xv.y + xv.z + xv.w;
    float ss = xv.x*xv.x + xv.y*xv.y + xv.z*xv.z + xv.w*xv.w;
    #pragma unroll
    for (int off = 16; off; off >>= 1) {
        s  += __shfl_xor_sync(0xffffffffu, s,  off);
        ss += __shfl_xor_sync(0xffffffffu, ss, off);
    }
    __shared__ float sh_s[8], sh_ss[8];
    if ((tid & 31) == 0) { sh_s[tid >> 5] = s; sh_ss[tid >> 5] = ss; }
    __syncthreads();
    if (tid < 32) {
        float a = (tid < 8) ? sh_s[tid]  : 0.f;
        float c = (tid < 8) ? sh_ss[tid] : 0.f;
        #pragma unroll
        for (int off = 4; off; off >>= 1) {
            a += __shfl_xor_sync(0xffffffffu, a, off);
            c += __shfl_xor_sync(0xffffffffu, c, off);
        }
        if (tid == 0) { sh_s[0] = a; sh_ss[0] = c; }
    }
    __syncthreads();
    float mu  = sh_s[0]  * (1.f / Dz);
    float var = sh_ss[0] * (1.f / Dz) - mu * mu;
    float inv = rsqrtf(var + 1e-5f);
    float4 gv = ((const float4*)g)[tid];
    float4 bv = ((const float4*)b)[tid];
    float4 o;
    o.x = (xv.x - mu) * inv * gv.x + bv.x;
    o.y = (xv.y - mu) * inv * gv.y + bv.y;
    o.z = (xv.z - mu) * inv * gv.z + bv.z;
    o.w = (xv.w - mu) * inv * gv.w + bv.w;
    __half hx = __float2half_rn(o.x), hy = __float2half_rn(o.y);
    __half hz = __float2half_rn(o.z), hw = __float2half_rn(o.w);
    __half2 p0; p0.x = hx; p0.y = hy;
    __half2 p1; p1.x = hz; p1.y = hw;
    uint2 u; u.x = *(uint32_t*)&p0; u.y = *(uint32_t*)&p1;
    ((uint2*)(O16 + (size_t)t * Dz))[tid] = u;
    if (SPLIT) {
        __half2 l0 = __floats2half2_rn(o.x - __half2float(hx), o.y - __half2float(hy));
        __half2 l1 = __floats2half2_rn(o.z - __half2float(hz), o.w - __half2float(hw));
        uint2 ul; ul.x = *(uint32_t*)&l0; ul.y = *(uint32_t*)&l1;
        ((uint2*)(OLO + (size_t)t * Dz))[tid] = ul;
    }
}

// ---------------------------------------------------------------------------
// fp16 tensor-core GEMM, cp.async.bulk staging, 512 threads (16 warps).
// Warp grid 4M x 4N, warp tile 32x32 -> 32 accumulators/warp, 50% occupancy
// at 2 CTAs/SM to cover ldmatrix->mma latency.
// C[M,N] = act(A @ B + bias)(+resid).
// GMODE: 0 dense; 2 A gathered via elist (>>ashift), C dense at e*Tz+m;
//        3 A dense at e*Tz+m, C scattered via elist.
// Staging: threads 0-127 bulk-copy one A row (128 B), 128-191 one B row
// (256 B); mbarrier count=192 (threads >=192 only wait). 3-stage ring.
// smem: 32 B mbarriers | A[3][128 x 144 B] | B[3][64 x 272 B].
// ---------------------------------------------------------------------------
#define GEMMH_SMEM (32 + 3*128*144 + 3*64*272)
template<int ACT, int GMODE, bool RESID, bool OUTH>
__global__ void __launch_bounds__(512,2) gemm_hc(
    const __half* __restrict__ A, const __half* __restrict__ B,
    const float* __restrict__ bias, void* __restrict__ Cv,
    int M, int N, int K,
    const float* __restrict__ resid,
    const int* __restrict__ elist, const int* __restrict__ cnt, int ashift)
{
    extern __shared__ __align__(16) char smraw[];
    uint32_t sb = s2u(smraw);
    uint32_t mb = sb;                       // 3 mbarriers (8 B each)
    uint32_t Au = sb + 32;
    uint32_t Bu = Au + 3*128*144;
    const uint32_t abuf = 128*144, bbuf = 64*272;

    int e = blockIdx.z;
    const __half* Bp = B + (size_t)e * K * N;
    const float*  bp = bias + (size_t)e * N;
    int mcount = (GMODE != 0) ? cnt[e] : M;
    int m0 = blockIdx.y * 128;
    if (m0 >= mcount) return;
    int n0 = blockIdx.x * 128;
    const int* lst = (GMODE != 0) ? (elist + e * Tz) : (const int*)nullptr;

    int tid = threadIdx.x;
    int lane = tid & 31, wid = tid >> 5;
    int warpM = wid >> 2, warpN = wid & 3;

    if (tid == 0) {
        mbar_init(mb, 192); mbar_init(mb + 8, 192); mbar_init(mb + 16, 192);
    }
    __syncthreads();

    // staging roles (threads 0-191)
    const __half* arow = nullptr; bool av = false; uint32_t ad = 0;
    const __half* brow = nullptr; uint32_t bd = 0;
    if (tid < 128) {
        int m = m0 + tid;
        av = (m < mcount);
        size_t rowg;
        if (GMODE == 2)      rowg = av ? (size_t)(lst[m] >> ashift) : 0;
        else if (GMODE == 3) rowg = av ? (size_t)(e * Tz + m) : 0;
        else                 rowg = av ? (size_t)m : 0;
        arow = A + rowg * (size_t)K;
        ad = Au + (uint32_t)tid * 144;
    } else if (tid < 192) {
        int r = tid - 128;
        brow = Bp + (size_t)r * N + n0;
        bd = Bu + (uint32_t)r * 272;
    }

    auto stage = [&](int kt2, int s){
        uint32_t m_ = mb + (uint32_t)s * 8;
        if (tid < 128) {
            if (av) { mbar_expect(m_, 128); cpbulk(ad + (uint32_t)s*abuf, arow + kt2*64, 128, m_); }
            else    { mbar_arrive(m_); }
        } else if (tid < 192) {
            mbar_expect(m_, 256);
            cpbulk(bd + (uint32_t)s*bbuf, brow + (size_t)(kt2*64)*N, 256, m_);
        }
    };

    float acc[2][4][4];
    #pragma unroll
    for (int i=0;i<2;i++)
        #pragma unroll
        for (int j=0;j<4;j++)
            #pragma unroll
            for (int l=0;l<4;l++) acc[i][j][l] = 0.f;

    int KT = K / 64;
    stage(0, 0); stage(1, 1); stage(2, 2);

    uint32_t lr = lane & 15, lc = (lane >> 4) * 8;
    for (int kt = 0; kt < KT; kt++) {
        int s = kt % 3;
        mbar_wait(mb + (uint32_t)s*8, (uint32_t)((kt/3) & 1));

        uint32_t abase = Au + (uint32_t)s*abuf + ((warpM*32 + lr)*72 + lc)*2;
        uint32_t bbase = Bu + (uint32_t)s*bbuf + (lr*136 + warpN*32 + lc)*2;
        #pragma unroll
        for (int ks = 0; ks < 4; ks++) {
            uint32_t ah[2][4];
            #pragma unroll
            for (int mt = 0; mt < 2; mt++)
                ldm4(ah[mt], abase + (mt*16*72 + ks*16)*2);
            uint32_t bt[2][4];
            #pragma unroll
            for (int pr = 0; pr < 2; pr++)
                ldm4t(bt[pr], bbase + (ks*16*136 + pr*16)*2);
            #pragma unroll
            for (int mt = 0; mt < 2; mt++) {
                mma16(acc[mt][0], ah[mt], bt[0][0], bt[0][1]);
                mma16(acc[mt][1], ah[mt], bt[0][2], bt[0][3]);
                mma16(acc[mt][2], ah[mt], bt[1][0], bt[1][1]);
                mma16(acc[mt][3], ah[mt], bt[1][2], bt[1][3]);
            }
        }
        __syncthreads();
        if (kt + 3 < KT) stage(kt + 3, s);
    }

    float2 bv[4];
    #pragma unroll
    for (int nt = 0; nt < 4; nt++)
        bv[nt] = *(const float2*)(bp + n0 + warpN*32 + (lane&3)*2 + nt*8);

    float*  Cf = (float*)Cv;
    __half* Ch = (__half*)Cv;
    #pragma unroll
    for (int mt = 0; mt < 2; mt++) {
        #pragma unroll
        for (int hf = 0; hf < 2; hf++) {
            int r = m0 + warpM*32 + mt*16 + (lane>>2) + hf*8;
            if (r >= mcount) continue;
            size_t crow;
            if (GMODE == 2)      crow = (size_t)(e * Tz + r);
            else if (GMODE == 3) crow = (size_t)lst[r];
            else                 crow = (size_t)r;
            int coff = n0 + warpN*32 + (lane&3)*2;
            const float* Rr = RESID ? (resid + crow*(size_t)N + coff) : (const float*)nullptr;
            #pragma unroll
            for (int nt = 0; nt < 4; nt++) {
                float v0 = acc[mt][nt][hf*2+0] + bv[nt].x;
                float v1 = acc[mt][nt][hf*2+1] + bv[nt].y;
                if (ACT == 1) { v0 = fmaxf(v0, 0.f); v1 = fmaxf(v1, 0.f); }
                if (ACT == 2) {
                    v0 = 0.5f*v0*(1.f + erff(v0*0.70710678118654752f));
                    v1 = 0.5f*v1*(1.f + erff(v1*0.70710678118654752f));
                }
                if (RESID) { v0 += Rr[nt*8]; v1 += Rr[nt*8+1]; }
                if (OUTH) {
                    __half2 h = __floats2half2_rn(v0, v1);
                    *(__half2*)(Ch + crow*(size_t)N + coff + nt*8) = h;
                } else {
                    float2 o; o.x = v0; o.y = v1;
                    *(float2*)(Cf + crow*(size_t)N + coff + nt*8) = o;
                }
            }
        }
    }
}

// ---------------------------------------------------------------------------
// Split-fp16 gate GEMM (near-fp32), cp.async staging (unchanged).
// ---------------------------------------------------------------------------
#define GATE_SMEM (2*2*128*40*2 + 2*2*32*136*2)
__global__ void __launch_bounds__(256,2) gemm_gate16(
    const __half* __restrict__ Ah, const __half* __restrict__ Al,
    const __half* __restrict__ Bh, const __half* __restrict__ Bl,
    const float* __restrict__ bias, float* __restrict__ C,
    int M, int N, int K)
{
    extern __shared__ __half smh[];
    __half* Ahs = smh;                        // [2][128][40]
    __half* Als = Ahs + 2*128*40;             // [2][128][40]
    __half* Bhs = Als + 2*128*40;             // [2][32][136]
    __half* Bls = Bhs + 2*32*136;             // [2][32][136]

    int m0 = blockIdx.y * 128;
    int n0 = blockIdx.x * 128;
    int tid = threadIdx.x;
    int lane = tid & 31, wid = tid >> 5;
    int warpM = wid >> 2, warpN = wid & 3;

    int arow = tid >> 1, acol = (tid & 1) * 16;
    const __half* ahp = Ah + (size_t)(m0 + arow) * K + acol;
    const __half* alp = Al + (size_t)(m0 + arow) * K + acol;
    uint32_t ahd = s2u(&Ahs[arow * 40 + acol]);
    uint32_t ald = s2u(&Als[arow * 40 + acol]);
    int brow = tid >> 3, bcol = (tid & 7) * 16;
    const __half* bhp = Bh + (size_t)brow * N + n0 + bcol;
    const __half* blp = Bl + (size_t)brow * N + n0 + bcol;
    uint32_t bhd = s2u(&Bhs[brow * 136 + bcol]);
    uint32_t bld = s2u(&Bls[brow * 136 + bcol]);

    const uint32_t abuf = 128*40*2, bbuf = 32*136*2;

    auto stage = [&](int kt, int buf){
        int k0 = kt * 32;
        cpa16(ahd + buf*abuf,      ahp + k0, true);
        cpa16(ahd + buf*abuf + 16, ahp + k0 + 8, true);
        cpa16(ald + buf*abuf,      alp + k0, true);
        cpa16(ald + buf*abuf + 16, alp + k0 + 8, true);
        cpa16(bhd + buf*bbuf,      bhp + (size_t)k0*N, true);
        cpa16(bhd + buf*bbuf + 16, bhp + (size_t)k0*N + 8, true);
        cpa16(bld + buf*bbuf,      blp + (size_t)k0*N, true);
        cpa16(bld + buf*bbuf + 16, blp + (size_t)k0*N + 8, true);
    };

    uint32_t ahs_u = s2u(Ahs), als_u = s2u(Als);
    uint32_t bhs_u = s2u(Bhs), bls_u = s2u(Bls);

    float acc[4][4][4];
    #pragma unroll
    for (int i=0;i<4;i++)
        #pragma unroll
        for (int j=0;j<4;j++)
            #pragma unroll
            for (int l=0;l<4;l++) acc[i][j][l] = 0.f;

    int KT = K / 32;
    stage(0, 0); cp_commit();

    uint32_t lr = lane & 15, lc = (lane >> 4) * 8;
    for (int kt = 0; kt < KT; kt++) {
        int buf = kt & 1;
        cp_wait0();
        __syncthreads();
        if (kt + 1 < KT) { stage(kt+1, buf ^ 1); }
        cp_commit();

        uint32_t aoff = ((uint32_t)buf*(128*40) + (warpM*64 + lr)*40 + lc)*2;
        uint32_t boff = ((uint32_t)buf*(32*136) + lr*136 + warpN*32 + lc)*2;
        #pragma unroll
        for (int ks = 0; ks < 2; ks++) {
            uint32_t ah[4][4], al[4][4];
            #pragma unroll
            for (int mt = 0; mt < 4; mt++) {
                ldm4(ah[mt], ahs_u + aoff + (mt*16*40 + ks*16)*2);
                ldm4(al[mt], als_u + aoff + (mt*16*40 + ks*16)*2);
            }
            uint32_t bth[2][4], btl[2][4];
            #pragma unroll
            for (int pr = 0; pr < 2; pr++) {
                ldm4t(bth[pr], bhs_u + boff + (ks*16*136 + pr*16)*2);
                ldm4t(btl[pr], bls_u + boff + (ks*16*136 + pr*16)*2);
            }
            #pragma unroll
            for (int mt = 0; mt < 4; mt++) {
                mma16(acc[mt][0], ah[mt], bth[0][0], bth[0][1]);
                mma16(acc[mt][1], ah[mt], bth[0][2], bth[0][3]);
                mma16(acc[mt][2], ah[mt], bth[1][0], bth[1][1]);
                mma16(acc[mt][3], ah[mt], bth[1][2], bth[1][3]);
                mma16(acc[mt][0], al[mt], bth[0][0], bth[0][1]);
                mma16(acc[mt][1], al[mt], bth[0][2], bth[0][3]);
                mma16(acc[mt][2], al[mt], bth[1][0], bth[1][1]);
                mma16(acc[mt][3], al[mt], bth[1][2], bth[1][3]);
                mma16(acc[mt][0], ah[mt], btl[0][0], btl[0][1]);
                mma16(acc[mt][1], ah[mt], btl[0][2], btl[0][3]);
                mma16(acc[mt][2], ah[mt], btl[1][0], btl[1][1]);
                mma16(acc[mt][3], ah[mt], btl[1][2], btl[1][3]);
            }
        }
    }

    float2 bv[4];
    #pragma unroll
    for (int nt = 0; nt < 4; nt++)
        bv[nt] = *(const float2*)(bias + n0 + warpN*32 + (lane&3)*2 + nt*8);

    #pragma unroll
    for (int mt = 0; mt < 4; mt++)
        #pragma unroll
        for (int hf = 0; hf < 2; hf++) {
            int r = m0 + warpM*64 + mt*16 + (lane>>2) + hf*8;
            float* Cr = C + (size_t)r*N + n0 + warpN*32 + (lane&3)*2;
            #pragma unroll
            for (int nt = 0; nt < 4; nt++) {
                float v0 = fmaxf(acc[mt][nt][hf*2+0] + bv[nt].x, 0.f);
                float v1 = fmaxf(acc[mt][nt][hf*2+1] + bv[nt].y, 0.f);
                float2 o; o.x = v0; o.y = v1;
                *(float2*)(Cr + nt*8) = o;
            }
        }
}

// ---------------------------------------------------------------------------
// Fused flash attention; K/V staged via cp.async.bulk + mbarrier (2-stage),
// Q via cp.async (one-shot). fp16 mma.sync, online softmax.
// ---------------------------------------------------------------------------
#define FA_SMEM (32 + 128*272 + 4*128*144)
__global__ void __launch_bounds__(256,2) fa_h(
    const __half* __restrict__ QKV, __half* __restrict__ O)
{
    extern __shared__ __align__(16) char smraw[];
    uint32_t sb = s2u(smraw);
    uint32_t mbr = sb;                 // 2 mbarriers
    uint32_t Pu  = sb + 32;            // [128][136] halves
    uint32_t Ku  = Pu + 128*272;       // [2][128][72] halves
    uint32_t Vu  = Ku + 2*128*144;
    const uint32_t kvbuf = 128*144;

    int bh = blockIdx.y, b = bh >> 4, h = bh & 15, g = h >> 1;
    int q0 = blockIdx.x * 128;
    int tid = threadIdx.x, lane = tid & 31, w = tid >> 5;

    if (tid == 0) { mbar_init(mbr, 256); mbar_init(mbr + 8, 256); }
    __syncthreads();

    // Q staging (cp.async, one group)
    const __half* Qb = QKV + (size_t)(b*Sz + q0) * QKVN + g*64;
    {
        int row = tid >> 1;
        #pragma unroll
        for (int j = 0; j < 4; j++) {
            int c = (tid & 1) + 2*j;
            cpa16(Pu + (uint32_t)row*144 + (uint32_t)c*16, Qb + (size_t)row*QKVN + c*8, true);
        }
    }
    cp_commit();

    const __half* Kb = QKV + (size_t)(b*Sz)*QKVN + 512 + h*64;
    const __half* Vb = QKV + (size_t)(b*Sz)*QKVN + 1536 + h*64;
    const __half* kvrow;
    uint32_t kvd;
    if (tid < 128) { kvrow = Kb + (size_t)tid*QKVN;        kvd = Ku + (uint32_t)tid*144; }
    else           { kvrow = Vb + (size_t)(tid-128)*QKVN;  kvd = Vu + (uint32_t)(tid-128)*144; }

    auto stageKV = [&](int kt, int s){
        uint32_t m_ = mbr + (uint32_t)s*8;
        mbar_expect(m_, 128);
        cpbulk(kvd + (uint32_t)s*kvbuf, kvrow + (size_t)(kt*128)*QKVN, 128, m_);
    };
    stageKV(0, 0);
    stageKV(1, 1);

    cp_wait0();
    __syncthreads();
    uint32_t lr = lane & 15, lc = (lane >> 4) * 8;
    uint32_t qbase = Pu + ((w*16 + lr)*72 + lc)*2;
    uint32_t qf[4][4];
    #pragma unroll
    for (int ks = 0; ks < 4; ks++) ldm4(qf[ks], qbase + ks*32);
    __syncthreads();   // Ps region reusable for P

    float m0 = -INFINITY, m1 = -INFINITY, l0 = 0.f, l1 = 0.f;
    float oacc[8][4];
    #pragma unroll
    for (int i=0;i<8;i++)
        #pragma unroll
        for (int j=0;j<4;j++) oacc[i][j] = 0.f;

    uint32_t pabase = Pu + ((w*16 + lr)*136 + lc)*2;
    uint32_t prow_u = Pu + ((w*16 + (lane>>2))*136 + (lane&3)*2)*2;
    __half* prow = (__half*)(smraw + (prow_u - sb));

    for (int kt = 0; kt < 8; kt++) {
        int s = kt & 1;
        mbar_wait(mbr + (uint32_t)s*8, (uint32_t)((kt >> 1) & 1));

        float sacc[16][4];
        #pragma unroll
        for (int i=0;i<16;i++)
            #pragma unroll
            for (int j=0;j<4;j++) sacc[i][j] = 0.f;
        uint32_t kbase = Ku + (uint32_t)s*kvbuf + (lr*72 + lc)*2;
        #pragma unroll
        for (int ks = 0; ks < 4; ks++) {
            #pragma unroll
            for (int np = 0; np < 8; np++) {
                uint32_t r[4];
                ldm4(r, kbase + (np*16*72 + ks*16)*2);
                mma16(sacc[2*np  ], qf[ks], r[0], r[2]);
                mma16(sacc[2*np+1], qf[ks], r[1], r[3]);
            }
        }

        float t0 = -INFINITY, t1 = -INFINITY;
        #pragma unroll
        for (int nt = 0; nt < 16; nt++) {
            t0 = fmaxf(t0, fmaxf(sacc[nt][0], sacc[nt][1]));
            t1 = fmaxf(t1, fmaxf(sacc[nt][2], sacc[nt][3]));
        }
        t0 = fmaxf(t0, __shfl_xor_sync(0xffffffffu, t0, 1));
        t0 = fmaxf(t0, __shfl_xor_sync(0xffffffffu, t0, 2));
        t1 = fmaxf(t1, __shfl_xor_sync(0xffffffffu, t1, 1));
        t1 = fmaxf(t1, __shfl_xor_sync(0xffffffffu, t1, 2));
        float mn0 = fmaxf(m0, t0), mn1 = fmaxf(m1, t1);
        float sc0 = __expf(m0 - mn0), sc1 = __expf(m1 - mn1);
        float s0 = 0.f, s1 = 0.f;
        #pragma unroll
        for (int nt = 0; nt < 16; nt++) {
            sacc[nt][0] = __expf(sacc[nt][0] - mn0);
            sacc[nt][1] = __expf(sacc[nt][1] - mn0);
            sacc[nt][2] = __expf(sacc[nt][2] - mn1);
            sacc[nt][3] = __expf(sacc[nt][3] - mn1);
            s0 += sacc[nt][0] + sacc[nt][1];
            s1 += sacc[nt][2] + sacc[nt][3];
        }
        s0 += __shfl_xor_sync(0xffffffffu, s0, 1);
        s0 += __shfl_xor_sync(0xffffffffu, s0, 2);
        s1 += __shfl_xor_sync(0xffffffffu, s1, 1);
        s1 += __shfl_xor_sync(0xffffffffu, s1, 2);
        l0 = l0*sc0 + s0; l1 = l1*sc1 + s1;
        m0 = mn0; m1 = mn1;
        #pragma unroll
        for (int nt = 0; nt < 8; nt++) {
            oacc[nt][0] *= sc0; oacc[nt][1] *= sc0;
            oacc[nt][2] *= sc1; oacc[nt][3] *= sc1;
        }

        #pragma unroll
        for (int nt = 0; nt < 16; nt++) {
            *(__half2*)(prow + nt*8)          = __floats2half2_rn(sacc[nt][0], sacc[nt][1]);
            *(__half2*)(prow + 8*136 + nt*8)  = __floats2half2_rn(sacc[nt][2], sacc[nt][3]);
        }
        __syncwarp();

        uint32_t vbase = Vu + (uint32_t)s*kvbuf + (lr*72 + lc)*2;
        #pragma unroll
        for (int k2 = 0; k2 < 8; k2++) {
            uint32_t pf[4];
            ldm4(pf, pabase + k2*32);
            #pragma unroll
            for (int hp = 0; hp < 4; hp++) {
                uint32_t vt[4];
                ldm4t(vt, vbase + (k2*16*72 + hp*16)*2);
                mma16(oacc[2*hp  ], pf, vt[0], vt[1]);
                mma16(oacc[2*hp+1], pf, vt[2], vt[3]);
            }
        }

        __syncthreads();
        if (kt + 2 < 8) stageKV(kt + 2, s);
    }

    float i0 = 1.f / l0, i1 = 1.f / l1;
    int r0 = q0 + w*16 + (lane >> 2);
    __half* Op = O + (size_t)(b*Sz + r0)*1024 + h*64 + (lane&3)*2;
    #pragma unroll
    for (int nt = 0; nt < 8; nt++) {
        *(__half2*)(Op + nt*8)          = __floats2half2_rn(oacc[nt][0]*i0, oacc[nt][1]*i0);
        *(__half2*)(Op + 8*1024 + nt*8) = __floats2half2_rn(oacc[nt][2]*i1, oacc[nt][3]*i1);
    }
}

// ---------------------------------------------------------------------------
// Gate head + softmax + top-2 + renorm + routing. One warp per token.
// ---------------------------------------------------------------------------
__global__ __launch_bounds__(256) void gate_route_kernel(
    const float* __restrict__ GH, const float* __restrict__ gw2,
    const float* __restrict__ gb2,
    float* __restrict__ wout, int* __restrict__ cnt, int* __restrict__ elist)
{
    int warp = threadIdx.x >> 5;
    int lane = threadIdx.x & 31;
    int t = blockIdx.x * 8 + warp;
    if (t >= Tz) return;

    float logit[Ez];
    #pragma unroll
    for (int o = 0; o < Ez; o++) {
        float s = 0.f;
        for (int i = lane; i < GHz; i += 32)
            s += GH[(size_t)t * GHz + i] * gw2[(size_t)i * Ez + o];
        #pragma unroll
        for (int off = 16; off; off >>= 1)
            s += __shfl_xor_sync(0xffffffffu, s, off);
        logit[o] = s + gb2[o];
    }
    if (lane == 0) {
        float m = logit[0];
        #pragma unroll
        for (int o = 1; o < Ez; o++) m = fmaxf(m, logit[o]);
        float w[Ez], sum = 0.f;
        #pragma unroll
        for (int o = 0; o < Ez; o++) { w[o] = expf(logit[o] - m); sum += w[o]; }
        float invs = 1.f / sum;
        #pragma unroll
        for (int o = 0; o < Ez; o++) w[o] *= invs;
        int i0 = 0; float v0 = w[0];
        #pragma unroll
        for (int o = 1; o < Ez; o++) if (w[o] > v0) { v0 = w[o]; i0 = o; }
        int i1 = -1; float v1 = -1.f;
        #pragma unroll
        for (int o = 0; o < Ez; o++)
            if (o != i0 && w[o] > v1) { v1 = w[o]; i1 = o; }
        float e1 = expf(v1 - v0);
        float den = 1.f + e1;
        wout[2*t + 0] = 1.f / den;
        wout[2*t + 1] = e1 / den;
        int p0 = atomicAdd(&cnt[i0], 1);
        elist[i0 * Tz + p0] = 2*t + 0;
        int p1 = atomicAdd(&cnt[i1], 1);
        elist[i1 * Tz + p1] = 2*t + 1;
    }
}

// ---------------------------------------------------------------------------
// Final combine: out = x1 + w0*eo[2t] + w1*eo[2t+1]  (eo fp16)
// ---------------------------------------------------------------------------
__global__ __launch_bounds__(256) void combine_kernel(
    const float* __restrict__ x1, const __half* __restrict__ eo,
    const float* __restrict__ w, float* __restrict__ out)
{
    int idx = blockIdx.x * 256 + threadIdx.x;
    int t = idx >> 8;
    int c = idx & 255;
    float w0 = w[2*t], w1 = w[2*t + 1];
    float4 a  = ((const float4*)x1)[idx];
    uint2 u0 = ((const uint2*)(eo + (size_t)(2*t)     * Dz))[c];
    uint2 u1 = ((const uint2*)(eo + (size_t)(2*t + 1) * Dz))[c];
    float2 e0a = __half22float2(*(__half2*)&u0.x);
    float2 e0b = __half22float2(*(__half2*)&u0.y);
    float2 e1a = __half22float2(*(__half2*)&u1.x);
    float2 e1b = __half22float2(*(__half2*)&u1.y);
    float4 r;
    r.x = a.x + w0 * e0a.x + w1 * e1a.x;
    r.y = a.y + w0 * e0a.y + w1 * e1a.y;
    r.z = a.z + w0 * e0b.x + w1 * e1b.x;
    r.w = a.w + w0 * e0b.y + w1 * e1b.y;
    ((float4*)out)[idx] = r;
}

// ---------------------------------------------------------------------------
// Host launch (single stream — graph-capture safe)
// ---------------------------------------------------------------------------
extern "C" void kernel_launch(void* const* d_in, const int* in_sizes, int n_in,
                              void* d_out, int out_size)
{
    const float* x    = (const float*)d_in[0];
    const float* wq   = (const float*)d_in[1];
    const float* bq   = (const float*)d_in[2];
    const float* wk   = (const float*)d_in[3];
    const float* bk   = (const float*)d_in[4];
    const float* wv   = (const float*)d_in[5];
    const float* bv   = (const float*)d_in[6];
    const float* wo   = (const float*)d_in[7];
    const float* bo   = (const float*)d_in[8];
    const float* ln1g = (const float*)d_in[9];
    const float* ln1b = (const float*)d_in[10];
    const float* ln2g = (const float*)d_in[11];
    const float* ln2b = (const float*)d_in[12];
    const float* gw1  = (const float*)d_in[13];
    const float* gb1  = (const float*)d_in[14];
    const float* gw2  = (const float*)d_in[15];
    const float* gb2  = (const float*)d_in[16];
    const float* ew1  = (const float*)d_in[17];
    const float* eb1  = (const float*)d_in[18];
    const float* ew2  = (const float*)d_in[19];
    const float* eb2  = (const float*)d_in[20];
    float* out = (float*)d_out;

    __half *h1h, *qkvh, *aoh, *h2h, *h2l, *hidh, *eo;
    __half *wqkvh, *woh, *ew1h, *ew2h, *gw1h, *gw1l;
    float *x1, *gh, *w, *qkvb;
    int *cnt, *elist;
    cudaGetSymbolAddress((void**)&h1h,  g_h1h);
    cudaGetSymbolAddress((void**)&qkvh, g_qkvh);
    cudaGetSymbolAddress((void**)&aoh,  g_aoh);
    cudaGetSymbolAddress((void**)&x1,   g_x1);
    cudaGetSymbolAddress((void**)&h2h,  g_h2h);
    cudaGetSymbolAddress((void**)&h2l,  g_h2l);
    cudaGetSymbolAddress((void**)&gh,   g_gh);
    cudaGetSymbolAddress((void**)&w,    g_w);
    cudaGetSymbolAddress((void**)&hidh, g_hidh);
    cudaGetSymbolAddress((void**)&eo,   g_eo);
    cudaGetSymbolAddress((void**)&cnt,  g_cnt);
    cudaGetSymbolAddress((void**)&elist,g_elist);
    cudaGetSymbolAddress((void**)&wqkvh,g_wqkvh);
    cudaGetSymbolAddress((void**)&woh,  g_woh);
    cudaGetSymbolAddress((void**)&ew1h, g_ew1h);
    cudaGetSymbolAddress((void**)&ew2h, g_ew2h);
    cudaGetSymbolAddress((void**)&gw1h, g_gw1h);
    cudaGetSymbolAddress((void**)&gw1l, g_gw1l);
    cudaGetSymbolAddress((void**)&qkvb, g_qkvb);

    cudaFuncSetAttribute(gemm_hc<0,0,false,true>, cudaFuncAttributeMaxDynamicSharedMemorySize, GEMMH_SMEM);
    cudaFuncSetAttribute(gemm_hc<0,0,true,false>, cudaFuncAttributeMaxDynamicSharedMemorySize, GEMMH_SMEM);
    cudaFuncSetAttribute(gemm_hc<2,2,false,true>, cudaFuncAttributeMaxDynamicSharedMemorySize, GEMMH_SMEM);
    cudaFuncSetAttribute(gemm_hc<0,3,false,true>, cudaFuncAttributeMaxDynamicSharedMemorySize, GEMMH_SMEM);
    cudaFuncSetAttribute(gemm_gate16, cudaFuncAttributeMaxDynamicSharedMemorySize, GATE_SMEM);
    cudaFuncSetAttribute(fa_h, cudaFuncAttributeMaxDynamicSharedMemorySize, FA_SMEM);

    // launch 0: fused qkv weight convert + bias pack + count zero
    cvt_qkv<<<(QKV_W4 + QKVN + Ez + 255)/256, 256>>>(
        wq, wk, wv, bq, bk, bv, wqkvh, qkvb, cnt);
    // launch 1: all remaining weight converts in one HBM-bound pass
    cvt_rest<<<(REST_TOTAL + 255)/256, 256>>>(
        wo, woh, gw1, gw1h, gw1l, ew1, ew1h, ew2, ew2h);

    // LN1
    ln_kernel<false><<<Tz, 256>>>(x, ln1g, ln1b, h1h, nullptr);

    // Fused QKV projection (512-thread GEMM)
    gemm_hc<0,0,false,true><<<dim3(QKVN/128, 32, 1), 512, GEMMH_SMEM>>>(
        h1h, wqkvh, qkvb, qkvh, Tz, QKVN, Dz, nullptr, nullptr, nullptr, 0);

    fa_h<<<dim3(Sz/128, Bz*Hh), 256, FA_SMEM>>>(qkvh, aoh);

    // Output projection + residual -> x1 fp32
    gemm_hc<0,0,true,false><<<dim3(8, 32, 1), 512, GEMMH_SMEM>>>(
        aoh, woh, bo, x1, Tz, Dz, Dz, x, nullptr, nullptr, 0);

    ln_kernel<true><<<Tz, 256>>>(x1, ln2g, ln2b, h2h, h2l);

    gemm_gate16<<<dim3(GHz/128, Tz/128, 1), 256, GATE_SMEM>>>(
        h2h, h2l, gw1h, gw1l, gb1, gh, Tz, GHz, Dz);

    gate_route_kernel<<<Tz/8, 256>>>(gh, gw2, gb2, w, cnt, elist);

    // Expert FFN: GEMM1 A-gathered / C-dense (hid rows e*Tz+m),
    //             GEMM2 A-dense / C-scattered (eo rows = assignment id)
    gemm_hc<2,2,false,true><<<dim3(EDz/128, Tz/128, Ez), 512, GEMMH_SMEM>>>(
        h2h, ew1h, eb1, hidh, Tz, EDz, Dz, nullptr, elist, cnt, 1);
    gemm_hc<0,3,false,true><<<dim3(Dz/128, Tz/128, Ez), 512, GEMMH_SMEM>>>(
        hidh, ew2h, eb2, eo, Tz, Dz, EDz, nullptr, elist, cnt, 0);

    combine_kernel<<<(Tz*Dz/4)/256, 256>>>(x1, eo, w, out);
}